// round 4
// baseline (speedup 1.0000x reference)
#include <cuda_runtime.h>
#include <math.h>

#define B_ 8
#define T_ 2048
#define E_ 1024

#define BM 128
#define BN 128
#define BK 16
#define LDSA 132
#define LDSB 132

// Scratch (allocation-free rule: __device__ globals)
__device__ float g_Q[(size_t)B_ * T_ * E_];
__device__ float g_K[(size_t)B_ * T_ * E_];
__device__ float g_V[(size_t)B_ * T_ * E_];
__device__ float g_S[(size_t)B_ * T_ * T_];

typedef unsigned long long ull;

__device__ __forceinline__ ull fma2(ull a, ull b, ull c) {
    ull d;
    asm("fma.rn.f32x2 %0, %1, %2, %3;" : "=l"(d) : "l"(a), "l"(b), "l"(c));
    return d;
}
__device__ __forceinline__ ull dup2(float x) {
    ull d;
    asm("mov.b64 %0, {%1, %1};" : "=l"(d) : "f"(x));
    return d;
}
__device__ __forceinline__ ull pack2(float lo, float hi) {
    ull d;
    asm("mov.b64 %0, {%1, %2};" : "=l"(d) : "f"(lo), "f"(hi));
    return d;
}
__device__ __forceinline__ float2 unpack2(ull x) {
    float2 r;
    asm("mov.b64 {%0, %1}, %2;" : "=f"(r.x), "=f"(r.y) : "l"(x));
    return r;
}

// C[m,n] = sum_k A[m,k] * B'[.,.]
// BTRANS==0: B is N x K row-major (C = A * B^T)   -- projections, scores
// BTRANS==1: B is K x N row-major (C = A * B)     -- attention * V
// If mask != nullptr: C = acc*scale, then mask[m*N+n]==0 -> -inf (scores epilogue)
template<int BTRANS>
__global__ __launch_bounds__(256, 2)
void gemm_kernel(const float* __restrict__ A, const float* __restrict__ Bp,
                 float* __restrict__ C, int M, int N, int K,
                 size_t sA, size_t sB, size_t sC,
                 const int* __restrict__ mask, float scale)
{
    __shared__ __align__(16) float As[BK * LDSA];
    __shared__ __align__(16) float Bs[BK * LDSB];

    A  += (size_t)blockIdx.z * sA;
    Bp += (size_t)blockIdx.z * sB;
    C  += (size_t)blockIdx.z * sC;

    const int tid  = threadIdx.x;
    const int mblk = blockIdx.y * BM;
    const int nblk = blockIdx.x * BN;

    // ---- global-load geometry ----
    const int alr = tid >> 2;          // 0..63  (tile row of first float4)
    const int alc = (tid & 3) << 2;    // 0,4,8,12 (k within tile)
    const float* Ag0 = A + (size_t)(mblk + alr) * K + alc;
    const float* Ag1 = Ag0 + (size_t)64 * K;

    const float* Bg0;
    const float* Bg1;
    int br = 0, bn4 = 0;
    if (BTRANS == 0) {
        Bg0 = Bp + (size_t)(nblk + alr) * K + alc;
        Bg1 = Bg0 + (size_t)64 * K;
    } else {
        br  = tid >> 5;                 // 0..7
        bn4 = (tid & 31) << 2;          // 0..124
        Bg0 = Bp + (size_t)br * N + nblk + bn4;
        Bg1 = Bg0 + (size_t)8 * N;
    }

    // ---- prologue load (k0 = 0) ----
    float4 pa0 = *(const float4*)(Ag0);
    float4 pa1 = *(const float4*)(Ag1);
    float4 pb0, pb1;
    if (BTRANS == 0) {
        pb0 = *(const float4*)(Bg0);
        pb1 = *(const float4*)(Bg1);
    } else {
        pb0 = *(const float4*)(Bg0);
        pb1 = *(const float4*)(Bg1);
    }

    const int tx = tid & 15, ty = tid >> 4;
    const int m0 = ty << 2, m1 = m0 + 64;
    const int n0 = tx << 2, n1 = n0 + 64;

    ull acc[8][4];
    #pragma unroll
    for (int i = 0; i < 8; ++i)
        #pragma unroll
        for (int j = 0; j < 4; ++j) acc[i][j] = 0ull;

    const int nk = K / BK;
    for (int kt = 0; kt < nk; ++kt) {
        // store prefetched tile to smem (A transposed to [k][m])
        As[(alc + 0) * LDSA + alr] = pa0.x;
        As[(alc + 1) * LDSA + alr] = pa0.y;
        As[(alc + 2) * LDSA + alr] = pa0.z;
        As[(alc + 3) * LDSA + alr] = pa0.w;
        As[(alc + 0) * LDSA + alr + 64] = pa1.x;
        As[(alc + 1) * LDSA + alr + 64] = pa1.y;
        As[(alc + 2) * LDSA + alr + 64] = pa1.z;
        As[(alc + 3) * LDSA + alr + 64] = pa1.w;
        if (BTRANS == 0) {
            Bs[(alc + 0) * LDSB + alr] = pb0.x;
            Bs[(alc + 1) * LDSB + alr] = pb0.y;
            Bs[(alc + 2) * LDSB + alr] = pb0.z;
            Bs[(alc + 3) * LDSB + alr] = pb0.w;
            Bs[(alc + 0) * LDSB + alr + 64] = pb1.x;
            Bs[(alc + 1) * LDSB + alr + 64] = pb1.y;
            Bs[(alc + 2) * LDSB + alr + 64] = pb1.z;
            Bs[(alc + 3) * LDSB + alr + 64] = pb1.w;
        } else {
            *(float4*)&Bs[br * LDSB + bn4]       = pb0;
            *(float4*)&Bs[(br + 8) * LDSB + bn4] = pb1;
        }
        __syncthreads();

        // prefetch next tile into registers (overlaps with compute)
        if (kt + 1 < nk) {
            const int k0 = (kt + 1) * BK;
            pa0 = *(const float4*)(Ag0 + k0);
            pa1 = *(const float4*)(Ag1 + k0);
            if (BTRANS == 0) {
                pb0 = *(const float4*)(Bg0 + k0);
                pb1 = *(const float4*)(Bg1 + k0);
            } else {
                pb0 = *(const float4*)(Bg0 + (size_t)k0 * N);
                pb1 = *(const float4*)(Bg1 + (size_t)k0 * N);
            }
        }

        #pragma unroll
        for (int kk = 0; kk < BK; ++kk) {
            float4 a0 = *(const float4*)&As[kk * LDSA + m0];
            float4 a1 = *(const float4*)&As[kk * LDSA + m1];
            float4 b0 = *(const float4*)&Bs[kk * LDSB + n0];
            float4 b1 = *(const float4*)&Bs[kk * LDSB + n1];
            ull bp0 = pack2(b0.x, b0.y);
            ull bp1 = pack2(b0.z, b0.w);
            ull bp2 = pack2(b1.x, b1.y);
            ull bp3 = pack2(b1.z, b1.w);
            float av[8] = {a0.x, a0.y, a0.z, a0.w, a1.x, a1.y, a1.z, a1.w};
            #pragma unroll
            for (int i = 0; i < 8; ++i) {
                ull ad = dup2(av[i]);
                acc[i][0] = fma2(ad, bp0, acc[i][0]);
                acc[i][1] = fma2(ad, bp1, acc[i][1]);
                acc[i][2] = fma2(ad, bp2, acc[i][2]);
                acc[i][3] = fma2(ad, bp3, acc[i][3]);
            }
        }
        __syncthreads();
    }

    const float NEG_INF = __int_as_float(0xff800000);
    #pragma unroll
    for (int i = 0; i < 8; ++i) {
        const int gm = mblk + ((i < 4) ? (m0 + i) : (m1 + i - 4));
        float* crow = C + (size_t)gm * N;
        #pragma unroll
        for (int j = 0; j < 4; ++j) {
            const int gn = nblk + ((j < 2) ? (n0 + j * 2) : (n1 + (j - 2) * 2));
            float2 p = unpack2(acc[i][j]);
            if (mask) {
                float v0 = p.x * scale;
                float v1 = p.y * scale;
                if (mask[(size_t)gm * N + gn] == 0)     v0 = NEG_INF;
                if (mask[(size_t)gm * N + gn + 1] == 0) v1 = NEG_INF;
                crow[gn]     = v0;
                crow[gn + 1] = v1;
            } else {
                crow[gn]     = p.x;
                crow[gn + 1] = p.y;
            }
        }
    }
}

// Row softmax over T_ = 2048 entries; one block (256 threads) per row.
__global__ void softmax_kernel(float* __restrict__ S)
{
    const int row = blockIdx.x;
    float* p = S + (size_t)row * T_;
    const int tid = threadIdx.x;

    float v[8];
    float mx = __int_as_float(0xff800000);
    #pragma unroll
    for (int i = 0; i < 8; ++i) {
        v[i] = p[tid + (i << 8)];
        mx = fmaxf(mx, v[i]);
    }
    __shared__ float smax[8];
    #pragma unroll
    for (int o = 16; o > 0; o >>= 1)
        mx = fmaxf(mx, __shfl_xor_sync(0xffffffff, mx, o));
    if ((tid & 31) == 0) smax[tid >> 5] = mx;
    __syncthreads();
    float rmax = fmaxf(fmaxf(fmaxf(smax[0], smax[1]), fmaxf(smax[2], smax[3])),
                       fmaxf(fmaxf(smax[4], smax[5]), fmaxf(smax[6], smax[7])));

    float sum = 0.0f;
    #pragma unroll
    for (int i = 0; i < 8; ++i) {
        v[i] = expf(v[i] - rmax);
        sum += v[i];
    }
    __shared__ float ssum[8];
    #pragma unroll
    for (int o = 16; o > 0; o >>= 1)
        sum += __shfl_xor_sync(0xffffffff, sum, o);
    if ((tid & 31) == 0) ssum[tid >> 5] = sum;
    __syncthreads();
    float tot = ssum[0] + ssum[1] + ssum[2] + ssum[3]
              + ssum[4] + ssum[5] + ssum[6] + ssum[7];
    float inv = 1.0f / tot;
    #pragma unroll
    for (int i = 0; i < 8; ++i)
        p[tid + (i << 8)] = v[i] * inv;
}

extern "C" void kernel_launch(void* const* d_in, const int* in_sizes, int n_in,
                              void* d_out, int out_size)
{
    const float* q    = (const float*)d_in[0];
    const float* k    = (const float*)d_in[1];
    const float* v    = (const float*)d_in[2];
    const int*   mask = (const int*)  d_in[3];
    const float* Wq   = (const float*)d_in[4];
    const float* Wk   = (const float*)d_in[5];
    const float* Wv   = (const float*)d_in[6];
    float* out = (float*)d_out;

    float *Q, *Kp, *V, *S;
    cudaGetSymbolAddress((void**)&Q,  g_Q);
    cudaGetSymbolAddress((void**)&Kp, g_K);
    cudaGetSymbolAddress((void**)&V,  g_V);
    cudaGetSymbolAddress((void**)&S,  g_S);

    dim3 blk(256);

    // QKV projections: C[m,o] = X[m,e] * W[o,e]^T, m = B*T flattened
    dim3 gproj(E_ / BN, (B_ * T_) / BM, 1);
    gemm_kernel<0><<<gproj, blk>>>(q, Wq, Q,  B_ * T_, E_, E_, 0, 0, 0, nullptr, 1.0f);
    gemm_kernel<0><<<gproj, blk>>>(k, Wk, Kp, B_ * T_, E_, E_, 0, 0, 0, nullptr, 1.0f);
    gemm_kernel<0><<<gproj, blk>>>(v, Wv, V,  B_ * T_, E_, E_, 0, 0, 0, nullptr, 1.0f);

    // scores[b,t,s] = Q[b,t,:] . K[b,s,:] / 32, masked -> -inf
    dim3 gsc(T_ / BN, T_ / BM, B_);
    gemm_kernel<0><<<gsc, blk>>>(Q, Kp, S, T_, T_, E_,
                                 (size_t)T_ * E_, (size_t)T_ * E_, (size_t)T_ * T_,
                                 mask, 0.03125f);

    // row softmax over s
    softmax_kernel<<<B_ * T_, 256>>>(S);

    // out[b,t,o] = P[b,t,:] . V[b,:,o]
    dim3 gav(E_ / BN, T_ / BM, B_);
    gemm_kernel<1><<<gav, blk>>>(S, V, out, T_, E_, T_,
                                 (size_t)T_ * T_, (size_t)T_ * E_, (size_t)T_ * E_,
                                 nullptr, 1.0f);
}

// round 8
// speedup vs baseline: 1.4920x; 1.4920x over previous
#include <cuda_runtime.h>
#include <cuda_bf16.h>
#include <stdint.h>
#include <math.h>

#define B_ 8
#define T_ 2048
#define E_ 1024

// ---- GEMM tiling ----
#define NSTAGE 3
#define ROWB 80              // smem row stride bytes (conflict-free for ldmatrix)
#define A_HI 0
#define A_LO 10240           // 128 * 80
#define B_HI 20480
#define B_LO 30720
#define STG_B 40960
#define SMEM_BYTES (NSTAGE * STG_B)

// ---------------- device scratch (allocation-free rule) ----------------
__device__ __align__(16) unsigned short g_qhi[(size_t)B_*T_*E_];
__device__ __align__(16) unsigned short g_qlo[(size_t)B_*T_*E_];
__device__ __align__(16) unsigned short g_khi[(size_t)B_*T_*E_];
__device__ __align__(16) unsigned short g_klo[(size_t)B_*T_*E_];
__device__ __align__(16) unsigned short g_vhi[(size_t)B_*T_*E_];
__device__ __align__(16) unsigned short g_vlo[(size_t)B_*T_*E_];
__device__ __align__(16) unsigned short g_Wqhi[(size_t)E_*E_];
__device__ __align__(16) unsigned short g_Wqlo[(size_t)E_*E_];
__device__ __align__(16) unsigned short g_Wkhi[(size_t)E_*E_];
__device__ __align__(16) unsigned short g_Wklo[(size_t)E_*E_];
__device__ __align__(16) unsigned short g_Wvhi[(size_t)E_*E_];
__device__ __align__(16) unsigned short g_Wvlo[(size_t)E_*E_];
__device__ __align__(16) unsigned short g_Qhi[(size_t)B_*T_*E_];
__device__ __align__(16) unsigned short g_Qlo[(size_t)B_*T_*E_];
__device__ __align__(16) unsigned short g_Khi[(size_t)B_*T_*E_];
__device__ __align__(16) unsigned short g_Klo[(size_t)B_*T_*E_];
__device__ __align__(16) unsigned short g_VThi[(size_t)B_*E_*T_];  // [b][o][t]
__device__ __align__(16) unsigned short g_VTlo[(size_t)B_*E_*T_];
__device__ __align__(16) float          g_S   [(size_t)B_*T_*T_];
__device__ __align__(16) unsigned short g_Phi [(size_t)B_*T_*T_];
__device__ __align__(16) unsigned short g_Plo [(size_t)B_*T_*T_];

// ---------------- helpers ----------------
__device__ __forceinline__ uint32_t smem_u32(const void* p) {
    uint32_t a;
    asm("{ .reg .u64 t; cvta.to.shared.u64 t, %1; cvt.u32.u64 %0, t; }" : "=r"(a) : "l"(p));
    return a;
}
__device__ __forceinline__ void cpasync16(uint32_t dst, const void* src) {
    asm volatile("cp.async.cg.shared.global [%0], [%1], 16;" :: "r"(dst), "l"(src) : "memory");
}
__device__ __forceinline__ void ldsm4(unsigned* r, uint32_t addr) {
    asm volatile("ldmatrix.sync.aligned.m8n8.x4.shared.b16 {%0,%1,%2,%3}, [%4];"
                 : "=r"(r[0]), "=r"(r[1]), "=r"(r[2]), "=r"(r[3]) : "r"(addr));
}
__device__ __forceinline__ void mma16816(float* c, const unsigned* a,
                                         unsigned b0, unsigned b1) {
    asm volatile(
        "mma.sync.aligned.m16n8k16.row.col.f32.bf16.bf16.f32 "
        "{%0,%1,%2,%3}, {%4,%5,%6,%7}, {%8,%9}, {%0,%1,%2,%3};"
        : "+f"(c[0]), "+f"(c[1]), "+f"(c[2]), "+f"(c[3])
        : "r"(a[0]), "r"(a[1]), "r"(a[2]), "r"(a[3]), "r"(b0), "r"(b1));
}
__device__ __forceinline__ void bsplit(float x, unsigned short& h, unsigned short& l) {
    __nv_bfloat16 bh = __float2bfloat16(x);
    float r = x - __bfloat162float(bh);
    __nv_bfloat16 bl = __float2bfloat16(r);
    h = __bfloat16_as_ushort(bh);
    l = __bfloat16_as_ushort(bl);
}

// ---------------- split fp32 -> (hi, lo) bf16 arrays ----------------
__global__ void split_kernel(const float4* __restrict__ x,
                             uint2* __restrict__ hi, uint2* __restrict__ lo, int n4)
{
    int i = blockIdx.x * blockDim.x + threadIdx.x;
    if (i >= n4) return;
    float4 v = x[i];
    float vv[4] = {v.x, v.y, v.z, v.w};
    unsigned short h[4], l[4];
    #pragma unroll
    for (int j = 0; j < 4; ++j) bsplit(vv[j], h[j], l[j]);
    uint2 hv, lv;
    hv.x = (unsigned)h[0] | ((unsigned)h[1] << 16);
    hv.y = (unsigned)h[2] | ((unsigned)h[3] << 16);
    lv.x = (unsigned)l[0] | ((unsigned)l[1] << 16);
    lv.y = (unsigned)l[2] | ((unsigned)l[3] << 16);
    hi[i] = hv;
    lo[i] = lv;
}

// ---------------- cp.async stage fill ----------------
// Pointers already offset to (row0, k0). All operands have row stride = K elems.
__device__ __forceinline__ void fill_stage(uint32_t sb,
    const unsigned short* __restrict__ Ah, const unsigned short* __restrict__ Al,
    const unsigned short* __restrict__ Bh, const unsigned short* __restrict__ Bl,
    int K, int tid)
{
    const int row = tid >> 1, h = tid & 1;
    const size_t off = (size_t)row * K + h * 16;
    const uint32_t d = sb + row * ROWB + h * 32;
    cpasync16(d + A_HI,      Ah + off);
    cpasync16(d + A_HI + 16, Ah + off + 8);
    cpasync16(d + A_LO,      Al + off);
    cpasync16(d + A_LO + 16, Al + off + 8);
    cpasync16(d + B_HI,      Bh + off);
    cpasync16(d + B_HI + 16, Bh + off + 8);
    cpasync16(d + B_LO,      Bl + off);
    cpasync16(d + B_LO + 16, Bl + off + 8);
}

// ---------------- split-bf16 3-pass NT GEMM (mma.sync path) ----------------
// C[m,n] = sum_k A[m,k]*B[n,k], A=(Ahi,Alo), B=(Bhi,Blo) bf16, fp32 accumulate,
// acc = Ahi*Bhi + Ahi*Blo + Alo*Bhi.
// EPI=0: split bf16 out (outHi/outLo u32 views, [M,N])
// EPI=1: transposed split bf16 out: [b][n][t] (V projection -> VT)
// EPI=2: v*scale, mask==0 -> -inf, fp32 out (scores)
// EPI=3: fp32 out (PV)
template<int EPI>
__global__ __launch_bounds__(256, 1)
void gemm_mma(const unsigned short* __restrict__ Ahi, const unsigned short* __restrict__ Alo,
              const unsigned short* __restrict__ Bhi, const unsigned short* __restrict__ Blo,
              float* __restrict__ outF, unsigned* __restrict__ outHi,
              unsigned* __restrict__ outLo,
              unsigned short* __restrict__ outTHi, unsigned short* __restrict__ outTLo,
              int N, int K, size_t sA, size_t sB, size_t sC,
              const int* __restrict__ mask, float scale)
{
    extern __shared__ char smem[];
    const uint32_t smb = smem_u32(smem);
    const int tid = threadIdx.x, lane = tid & 31, wid = tid >> 5;
    const int wm = wid & 1, wn = wid >> 1;          // 2 x 4 warp grid
    const int mblk = blockIdx.y << 7, nblk = blockIdx.x << 7;
    const size_t bz = blockIdx.z;

    const unsigned short* pAh = Ahi + bz * sA + (size_t)mblk * K;
    const unsigned short* pAl = Alo + bz * sA + (size_t)mblk * K;
    const unsigned short* pBh = Bhi + bz * sB + (size_t)nblk * K;
    const unsigned short* pBl = Blo + bz * sB + (size_t)nblk * K;

    float acc[4][4][4];
    #pragma unroll
    for (int i = 0; i < 4; ++i)
        #pragma unroll
        for (int j = 0; j < 4; ++j)
            #pragma unroll
            for (int e = 0; e < 4; ++e) acc[i][j][e] = 0.0f;

    const int nk = K >> 5;

    // prologue: stages 0 .. NSTAGE-2
    #pragma unroll
    for (int s = 0; s < NSTAGE - 1; ++s) {
        fill_stage(smb + s * STG_B, pAh + s * 32, pAl + s * 32,
                   pBh + s * 32, pBl + s * 32, K, tid);
        asm volatile("cp.async.commit_group;" ::: "memory");
    }

    const int lrow = lane & 15;
    const uint32_t lcoff = (lane >> 4) << 4;   // 0 or 16 bytes

    for (int kt = 0; kt < nk; ++kt) {
        asm volatile("cp.async.wait_group 1;" ::: "memory");
        __syncthreads();

        const int s2 = kt + NSTAGE - 1;
        if (s2 < nk) {
            fill_stage(smb + (s2 % NSTAGE) * STG_B,
                       pAh + s2 * 32, pAl + s2 * 32,
                       pBh + s2 * 32, pBl + s2 * 32, K, tid);
        }
        asm volatile("cp.async.commit_group;" ::: "memory");

        const uint32_t sb = smb + (kt % NSTAGE) * STG_B;
        #pragma unroll
        for (int ks = 0; ks < 2; ++ks) {
            const uint32_t koff = (ks << 5) + lcoff;
            unsigned ah[4][4], al[4][4], bh[2][4], bl[2][4];
            #pragma unroll
            for (int mf = 0; mf < 4; ++mf) {
                uint32_t r = sb + (uint32_t)(wm * 64 + mf * 16 + lrow) * ROWB + koff;
                ldsm4(ah[mf], r + A_HI);
                ldsm4(al[mf], r + A_LO);
            }
            #pragma unroll
            for (int nf2 = 0; nf2 < 2; ++nf2) {
                uint32_t r = sb + (uint32_t)(wn * 32 + nf2 * 16 + lrow) * ROWB + koff;
                ldsm4(bh[nf2], r + B_HI);
                ldsm4(bl[nf2], r + B_LO);
            }
            #pragma unroll
            for (int mf = 0; mf < 4; ++mf) {
                #pragma unroll
                for (int nf = 0; nf < 4; ++nf) {
                    const int g = nf >> 1, s = nf & 1;
                    mma16816(acc[mf][nf], ah[mf], bh[g][s], bh[g][s + 2]);
                    mma16816(acc[mf][nf], ah[mf], bl[g][s], bl[g][s + 2]);
                    mma16816(acc[mf][nf], al[mf], bh[g][s], bh[g][s + 2]);
                }
            }
        }
    }

    // ---------------- epilogue ----------------
    const float NEG_INF = __int_as_float(0xff800000);
    const int mbase = mblk + wm * 64 + (lane >> 2);
    const int nbase = nblk + wn * 32 + ((lane & 3) << 1);
    #pragma unroll
    for (int mf = 0; mf < 4; ++mf) {
        #pragma unroll
        for (int nf = 0; nf < 4; ++nf) {
            const float* c = acc[mf][nf];
            const int r0 = mbase + mf * 16;
            const int c0 = nbase + nf * 8;
            if (EPI == 2) {
                const int2 m0 = *(const int2*)(mask + (size_t)r0 * N + c0);
                const int2 m1 = *(const int2*)(mask + (size_t)(r0 + 8) * N + c0);
                float2 o0, o1;
                o0.x = m0.x ? c[0] * scale : NEG_INF;
                o0.y = m0.y ? c[1] * scale : NEG_INF;
                o1.x = m1.x ? c[2] * scale : NEG_INF;
                o1.y = m1.y ? c[3] * scale : NEG_INF;
                *(float2*)(outF + bz * sC + (size_t)r0 * N + c0)       = o0;
                *(float2*)(outF + bz * sC + (size_t)(r0 + 8) * N + c0) = o1;
            } else if (EPI == 3) {
                float2 o0 = make_float2(c[0], c[1]);
                float2 o1 = make_float2(c[2], c[3]);
                *(float2*)(outF + bz * sC + (size_t)r0 * N + c0)       = o0;
                *(float2*)(outF + bz * sC + (size_t)(r0 + 8) * N + c0) = o1;
            } else if (EPI == 0) {
                unsigned short h0, l0, h1, l1;
                bsplit(c[0], h0, l0);
                bsplit(c[1], h1, l1);
                outHi[((size_t)r0 * N + c0) >> 1] = (unsigned)h0 | ((unsigned)h1 << 16);
                outLo[((size_t)r0 * N + c0) >> 1] = (unsigned)l0 | ((unsigned)l1 << 16);
                bsplit(c[2], h0, l0);
                bsplit(c[3], h1, l1);
                outHi[((size_t)(r0 + 8) * N + c0) >> 1] = (unsigned)h0 | ((unsigned)h1 << 16);
                outLo[((size_t)(r0 + 8) * N + c0) >> 1] = (unsigned)l0 | ((unsigned)l1 << 16);
            } else {  // EPI == 1: VT[b][o][t]
                #pragma unroll
                for (int e = 0; e < 4; ++e) {
                    const int r = r0 + (e >> 1) * 8;
                    const int o = c0 + (e & 1);
                    unsigned short h, l;
                    bsplit(c[e], h, l);
                    const size_t idx = (((size_t)(r >> 11)) * E_ + o) * T_ + (r & (T_ - 1));
                    outTHi[idx] = h;
                    outTLo[idx] = l;
                }
            }
        }
    }
}

// ---------------- softmax: fp32 S row -> split bf16 P ----------------
__global__ void softmax_split_kernel(const float* __restrict__ S,
                                     uint4* __restrict__ Phi, uint4* __restrict__ Plo)
{
    const int row = blockIdx.x, tid = threadIdx.x;
    const float4* src = (const float4*)(S + (size_t)row * T_);
    float4 a = src[tid * 2], b2 = src[tid * 2 + 1];
    float v[8] = {a.x, a.y, a.z, a.w, b2.x, b2.y, b2.z, b2.w};

    float mx = v[0];
    #pragma unroll
    for (int i = 1; i < 8; ++i) mx = fmaxf(mx, v[i]);
    __shared__ float red[8];
    #pragma unroll
    for (int o = 16; o > 0; o >>= 1) mx = fmaxf(mx, __shfl_xor_sync(0xffffffff, mx, o));
    if ((tid & 31) == 0) red[tid >> 5] = mx;
    __syncthreads();
    float rmax = fmaxf(fmaxf(fmaxf(red[0], red[1]), fmaxf(red[2], red[3])),
                       fmaxf(fmaxf(red[4], red[5]), fmaxf(red[6], red[7])));
    __syncthreads();

    float sum = 0.0f;
    #pragma unroll
    for (int i = 0; i < 8; ++i) { v[i] = expf(v[i] - rmax); sum += v[i]; }
    #pragma unroll
    for (int o = 16; o > 0; o >>= 1) sum += __shfl_xor_sync(0xffffffff, sum, o);
    if ((tid & 31) == 0) red[tid >> 5] = sum;
    __syncthreads();
    float tot = red[0] + red[1] + red[2] + red[3] + red[4] + red[5] + red[6] + red[7];
    float inv = 1.0f / tot;

    unsigned hw[4], lw[4];
    #pragma unroll
    for (int j = 0; j < 4; ++j) {
        unsigned short h0, l0, h1, l1;
        bsplit(v[2 * j] * inv, h0, l0);
        bsplit(v[2 * j + 1] * inv, h1, l1);
        hw[j] = (unsigned)h0 | ((unsigned)h1 << 16);
        lw[j] = (unsigned)l0 | ((unsigned)l1 << 16);
    }
    Phi[(size_t)row * (T_ / 8) + tid] = make_uint4(hw[0], hw[1], hw[2], hw[3]);
    Plo[(size_t)row * (T_ / 8) + tid] = make_uint4(lw[0], lw[1], lw[2], lw[3]);
}

// ---------------- driver ----------------
extern "C" void kernel_launch(void* const* d_in, const int* in_sizes, int n_in,
                              void* d_out, int out_size)
{
    const float* q    = (const float*)d_in[0];
    const float* k    = (const float*)d_in[1];
    const float* v    = (const float*)d_in[2];
    const int*   mask = (const int*)  d_in[3];
    const float* Wq   = (const float*)d_in[4];
    const float* Wk   = (const float*)d_in[5];
    const float* Wv   = (const float*)d_in[6];
    float* out = (float*)d_out;

    unsigned short *qhi, *qlo, *khi, *klo, *vhi, *vlo;
    unsigned short *Wqhi, *Wqlo, *Wkhi, *Wklo, *Wvhi, *Wvlo;
    unsigned short *Qhi, *Qlo, *Khi, *Klo, *VThi, *VTlo, *Phi, *Plo;
    float* S;
    cudaGetSymbolAddress((void**)&qhi,  g_qhi);
    cudaGetSymbolAddress((void**)&qlo,  g_qlo);
    cudaGetSymbolAddress((void**)&khi,  g_khi);
    cudaGetSymbolAddress((void**)&klo,  g_klo);
    cudaGetSymbolAddress((void**)&vhi,  g_vhi);
    cudaGetSymbolAddress((void**)&vlo,  g_vlo);
    cudaGetSymbolAddress((void**)&Wqhi, g_Wqhi);
    cudaGetSymbolAddress((void**)&Wqlo, g_Wqlo);
    cudaGetSymbolAddress((void**)&Wkhi, g_Wkhi);
    cudaGetSymbolAddress((void**)&Wklo, g_Wklo);
    cudaGetSymbolAddress((void**)&Wvhi, g_Wvhi);
    cudaGetSymbolAddress((void**)&Wvlo, g_Wvlo);
    cudaGetSymbolAddress((void**)&Qhi,  g_Qhi);
    cudaGetSymbolAddress((void**)&Qlo,  g_Qlo);
    cudaGetSymbolAddress((void**)&Khi,  g_Khi);
    cudaGetSymbolAddress((void**)&Klo,  g_Klo);
    cudaGetSymbolAddress((void**)&VThi, g_VThi);
    cudaGetSymbolAddress((void**)&VTlo, g_VTlo);
    cudaGetSymbolAddress((void**)&S,    g_S);
    cudaGetSymbolAddress((void**)&Phi,  g_Phi);
    cudaGetSymbolAddress((void**)&Plo,  g_Plo);

    cudaFuncSetAttribute(gemm_mma<0>, cudaFuncAttributeMaxDynamicSharedMemorySize, SMEM_BYTES);
    cudaFuncSetAttribute(gemm_mma<1>, cudaFuncAttributeMaxDynamicSharedMemorySize, SMEM_BYTES);
    cudaFuncSetAttribute(gemm_mma<2>, cudaFuncAttributeMaxDynamicSharedMemorySize, SMEM_BYTES);
    cudaFuncSetAttribute(gemm_mma<3>, cudaFuncAttributeMaxDynamicSharedMemorySize, SMEM_BYTES);

    const int nx = B_ * T_ * E_ / 4;
    const int nw = E_ * E_ / 4;
    split_kernel<<<(nx + 255) / 256, 256>>>((const float4*)q,  (uint2*)qhi,  (uint2*)qlo,  nx);
    split_kernel<<<(nx + 255) / 256, 256>>>((const float4*)k,  (uint2*)khi,  (uint2*)klo,  nx);
    split_kernel<<<(nx + 255) / 256, 256>>>((const float4*)v,  (uint2*)vhi,  (uint2*)vlo,  nx);
    split_kernel<<<(nw + 255) / 256, 256>>>((const float4*)Wq, (uint2*)Wqhi, (uint2*)Wqlo, nw);
    split_kernel<<<(nw + 255) / 256, 256>>>((const float4*)Wk, (uint2*)Wkhi, (uint2*)Wklo, nw);
    split_kernel<<<(nw + 255) / 256, 256>>>((const float4*)Wv, (uint2*)Wvhi, (uint2*)Wvlo, nw);

    // projections: [B*T, E] = [B*T, E] x [E, E]^T
    dim3 gp(E_ / 128, (B_ * T_) / 128, 1);
    gemm_mma<0><<<gp, 256, SMEM_BYTES>>>(qhi, qlo, Wqhi, Wqlo,
        nullptr, (unsigned*)Qhi, (unsigned*)Qlo, nullptr, nullptr,
        E_, E_, 0, 0, 0, nullptr, 0.f);
    gemm_mma<0><<<gp, 256, SMEM_BYTES>>>(khi, klo, Wkhi, Wklo,
        nullptr, (unsigned*)Khi, (unsigned*)Klo, nullptr, nullptr,
        E_, E_, 0, 0, 0, nullptr, 0.f);
    gemm_mma<1><<<gp, 256, SMEM_BYTES>>>(vhi, vlo, Wvhi, Wvlo,
        nullptr, nullptr, nullptr, VThi, VTlo,
        E_, E_, 0, 0, 0, nullptr, 0.f);

    // scores: per batch [T,T] = Q x K^T, scaled + masked
    dim3 gs(T_ / 128, T_ / 128, B_);
    gemm_mma<2><<<gs, 256, SMEM_BYTES>>>(Qhi, Qlo, Khi, Klo,
        S, nullptr, nullptr, nullptr, nullptr,
        T_, E_, (size_t)T_ * E_, (size_t)T_ * E_, (size_t)T_ * T_, mask, 0.03125f);

    softmax_split_kernel<<<B_ * T_, 256>>>(S, (uint4*)Phi, (uint4*)Plo);

    // out: per batch [T,E] = P x VT^T  (VT stored [o][t])
    dim3 gv(E_ / 128, T_ / 128, B_);
    gemm_mma<3><<<gv, 256, SMEM_BYTES>>>(Phi, Plo, VThi, VTlo,
        out, nullptr, nullptr, nullptr, nullptr,
        E_, T_, (size_t)T_ * T_, (size_t)E_ * T_, (size_t)T_ * E_, nullptr, 1.f);
}

// round 9
// speedup vs baseline: 1.6183x; 1.0847x over previous
#include <cuda_runtime.h>
#include <cuda_bf16.h>
#include <stdint.h>
#include <math.h>

#define B_ 8
#define T_ 2048
#define E_ 1024

// ---- GEMM tiling: CTA 128M x 256N, 8 warps (2x4), warp tile 64x64, BK=32 ----
#define NSTAGE 3
#define ROWB 80              // smem row stride bytes (64B data + 16 pad; conflict-free ldmatrix)
#define A_HI 0
#define A_LO 10240           // 128 * 80
#define B_HI 20480
#define B_LO 40960           // B region: 256 rows * 80
#define STG_B 61440
#define SMEM_BYTES (NSTAGE * STG_B)

// ---------------- device scratch (allocation-free rule) ----------------
__device__ __align__(16) unsigned short g_qhi[(size_t)B_*T_*E_];
__device__ __align__(16) unsigned short g_qlo[(size_t)B_*T_*E_];
__device__ __align__(16) unsigned short g_khi[(size_t)B_*T_*E_];
__device__ __align__(16) unsigned short g_klo[(size_t)B_*T_*E_];
__device__ __align__(16) unsigned short g_vhi[(size_t)B_*T_*E_];
__device__ __align__(16) unsigned short g_vlo[(size_t)B_*T_*E_];
__device__ __align__(16) unsigned short g_Wqhi[(size_t)E_*E_];
__device__ __align__(16) unsigned short g_Wqlo[(size_t)E_*E_];
__device__ __align__(16) unsigned short g_Wkhi[(size_t)E_*E_];
__device__ __align__(16) unsigned short g_Wklo[(size_t)E_*E_];
__device__ __align__(16) unsigned short g_Wvhi[(size_t)E_*E_];
__device__ __align__(16) unsigned short g_Wvlo[(size_t)E_*E_];
__device__ __align__(16) unsigned short g_Qhi[(size_t)B_*T_*E_];
__device__ __align__(16) unsigned short g_Qlo[(size_t)B_*T_*E_];
__device__ __align__(16) unsigned short g_Khi[(size_t)B_*T_*E_];
__device__ __align__(16) unsigned short g_Klo[(size_t)B_*T_*E_];
__device__ __align__(16) unsigned short g_VThi[(size_t)B_*E_*T_];  // [b][o][t]
__device__ __align__(16) unsigned short g_VTlo[(size_t)B_*E_*T_];
__device__ __align__(16) float          g_S   [(size_t)B_*T_*T_];
__device__ __align__(16) unsigned short g_Phi [(size_t)B_*T_*T_];
__device__ __align__(16) unsigned short g_Plo [(size_t)B_*T_*T_];

// ---------------- helpers ----------------
__device__ __forceinline__ uint32_t smem_u32(const void* p) {
    uint32_t a;
    asm("{ .reg .u64 t; cvta.to.shared.u64 t, %1; cvt.u32.u64 %0, t; }" : "=r"(a) : "l"(p));
    return a;
}
__device__ __forceinline__ void cpasync16(uint32_t dst, const void* src) {
    asm volatile("cp.async.cg.shared.global [%0], [%1], 16;" :: "r"(dst), "l"(src) : "memory");
}
__device__ __forceinline__ void ldsm4(unsigned* r, uint32_t addr) {
    asm volatile("ldmatrix.sync.aligned.m8n8.x4.shared.b16 {%0,%1,%2,%3}, [%4];"
                 : "=r"(r[0]), "=r"(r[1]), "=r"(r[2]), "=r"(r[3]) : "r"(addr));
}
__device__ __forceinline__ void mma16816(float* c, const unsigned* a,
                                         unsigned b0, unsigned b1) {
    asm volatile(
        "mma.sync.aligned.m16n8k16.row.col.f32.bf16.bf16.f32 "
        "{%0,%1,%2,%3}, {%4,%5,%6,%7}, {%8,%9}, {%0,%1,%2,%3};"
        : "+f"(c[0]), "+f"(c[1]), "+f"(c[2]), "+f"(c[3])
        : "r"(a[0]), "r"(a[1]), "r"(a[2]), "r"(a[3]), "r"(b0), "r"(b1));
}
__device__ __forceinline__ void bsplit(float x, unsigned short& h, unsigned short& l) {
    __nv_bfloat16 bh = __float2bfloat16(x);
    float r = x - __bfloat162float(bh);
    __nv_bfloat16 bl = __float2bfloat16(r);
    h = __bfloat16_as_ushort(bh);
    l = __bfloat16_as_ushort(bl);
}

// ---------------- split fp32 -> (hi, lo) bf16 arrays ----------------
__global__ void split_kernel(const float4* __restrict__ x,
                             uint2* __restrict__ hi, uint2* __restrict__ lo, int n4)
{
    int i = blockIdx.x * blockDim.x + threadIdx.x;
    if (i >= n4) return;
    float4 v = x[i];
    float vv[4] = {v.x, v.y, v.z, v.w};
    unsigned short h[4], l[4];
    #pragma unroll
    for (int j = 0; j < 4; ++j) bsplit(vv[j], h[j], l[j]);
    uint2 hv, lv;
    hv.x = (unsigned)h[0] | ((unsigned)h[1] << 16);
    hv.y = (unsigned)h[2] | ((unsigned)h[3] << 16);
    lv.x = (unsigned)l[0] | ((unsigned)l[1] << 16);
    lv.y = (unsigned)l[2] | ((unsigned)l[3] << 16);
    hi[i] = hv;
    lo[i] = lv;
}

// ---------------- cp.async stage fill ----------------
// A: 128 rows x 32 K (hi/lo), B: 256 rows x 32 K (hi/lo). Row = 64B = 4 chunks of 16B.
__device__ __forceinline__ void fill_stage(uint32_t sb,
    const unsigned short* __restrict__ Ah, const unsigned short* __restrict__ Al,
    const unsigned short* __restrict__ Bh, const unsigned short* __restrict__ Bl,
    int K, int tid)
{
    #pragma unroll
    for (int i = 0; i < 2; ++i) {                       // A: 512 chunks each half
        const int idx = (i << 8) + tid;
        const int row = idx >> 2, ch = idx & 3;
        const size_t off = (size_t)row * K + ch * 8;
        const uint32_t d = sb + row * ROWB + ch * 16;
        cpasync16(d + A_HI, Ah + off);
        cpasync16(d + A_LO, Al + off);
    }
    #pragma unroll
    for (int i = 0; i < 4; ++i) {                       // B: 1024 chunks each half
        const int idx = (i << 8) + tid;
        const int row = idx >> 2, ch = idx & 3;
        const size_t off = (size_t)row * K + ch * 8;
        const uint32_t d = sb + row * ROWB + ch * 16;
        cpasync16(d + B_HI, Bh + off);
        cpasync16(d + B_LO, Bl + off);
    }
}

// ---------------- split-bf16 3-pass NT GEMM (mma.sync path) ----------------
// C[m,n] = sum_k A[m,k]*B[n,k]; acc = Ahi*Bhi + Ahi*Blo + Alo*Bhi (fp32 acc).
// EPI=0: split bf16 out ([M,N])   EPI=1: transposed split bf16 out [b][n][t]
// EPI=2: v*scale, mask==0 -> -inf, fp32 out   EPI=3: fp32 out
template<int EPI>
__global__ __launch_bounds__(256, 1)
void gemm_mma(const unsigned short* __restrict__ Ahi, const unsigned short* __restrict__ Alo,
              const unsigned short* __restrict__ Bhi, const unsigned short* __restrict__ Blo,
              float* __restrict__ outF, unsigned* __restrict__ outHi,
              unsigned* __restrict__ outLo,
              unsigned short* __restrict__ outTHi, unsigned short* __restrict__ outTLo,
              int N, int K, size_t sA, size_t sB, size_t sC,
              const int* __restrict__ mask, float scale)
{
    extern __shared__ char smem[];
    const uint32_t smb = smem_u32(smem);
    const int tid = threadIdx.x, lane = tid & 31, wid = tid >> 5;
    const int wm = wid & 1, wn = wid >> 1;          // 2 x 4 warp grid, warp tile 64x64
    const int mblk = blockIdx.y << 7, nblk = blockIdx.x << 8;
    const size_t bz = blockIdx.z;

    const unsigned short* pAh = Ahi + bz * sA + (size_t)mblk * K;
    const unsigned short* pAl = Alo + bz * sA + (size_t)mblk * K;
    const unsigned short* pBh = Bhi + bz * sB + (size_t)nblk * K;
    const unsigned short* pBl = Blo + bz * sB + (size_t)nblk * K;

    float acc[4][8][4];
    #pragma unroll
    for (int i = 0; i < 4; ++i)
        #pragma unroll
        for (int j = 0; j < 8; ++j)
            #pragma unroll
            for (int e = 0; e < 4; ++e) acc[i][j][e] = 0.0f;

    const int nk = K >> 5;

    #pragma unroll
    for (int s = 0; s < NSTAGE - 1; ++s) {
        fill_stage(smb + s * STG_B, pAh + s * 32, pAl + s * 32,
                   pBh + s * 32, pBl + s * 32, K, tid);
        asm volatile("cp.async.commit_group;" ::: "memory");
    }

    const int lrow = lane & 15;
    const uint32_t lcoff = (lane >> 4) << 4;   // 0 or 16 bytes

    for (int kt = 0; kt < nk; ++kt) {
        asm volatile("cp.async.wait_group 1;" ::: "memory");
        __syncthreads();

        const int s2 = kt + NSTAGE - 1;
        if (s2 < nk) {
            fill_stage(smb + (s2 % NSTAGE) * STG_B,
                       pAh + s2 * 32, pAl + s2 * 32,
                       pBh + s2 * 32, pBl + s2 * 32, K, tid);
        }
        asm volatile("cp.async.commit_group;" ::: "memory");

        const uint32_t sb = smb + (kt % NSTAGE) * STG_B;
        #pragma unroll
        for (int ks = 0; ks < 2; ++ks) {
            const uint32_t koff = (ks << 5) + lcoff;
            unsigned ah[4][4], al[4][4], bh[4][4], bl[4][4];
            #pragma unroll
            for (int mf = 0; mf < 4; ++mf) {
                uint32_t r = sb + (uint32_t)(wm * 64 + mf * 16 + lrow) * ROWB + koff;
                ldsm4(ah[mf], r + A_HI);
                ldsm4(al[mf], r + A_LO);
            }
            #pragma unroll
            for (int nf2 = 0; nf2 < 4; ++nf2) {
                uint32_t r = sb + (uint32_t)(wn * 64 + nf2 * 16 + lrow) * ROWB + koff;
                ldsm4(bh[nf2], r + B_HI);
                ldsm4(bl[nf2], r + B_LO);
            }
            #pragma unroll
            for (int mf = 0; mf < 4; ++mf) {
                #pragma unroll
                for (int nf = 0; nf < 8; ++nf) {
                    const int g = nf >> 1, s = nf & 1;
                    mma16816(acc[mf][nf], ah[mf], bh[g][s], bh[g][s + 2]);
                    mma16816(acc[mf][nf], ah[mf], bl[g][s], bl[g][s + 2]);
                    mma16816(acc[mf][nf], al[mf], bh[g][s], bh[g][s + 2]);
                }
            }
        }
    }

    // ---------------- epilogue ----------------
    const float NEG_INF = __int_as_float(0xff800000);
    const int mbase = mblk + wm * 64 + (lane >> 2);
    const int nbase = nblk + wn * 64 + ((lane & 3) << 1);
    #pragma unroll
    for (int mf = 0; mf < 4; ++mf) {
        #pragma unroll
        for (int nf = 0; nf < 8; ++nf) {
            const float* c = acc[mf][nf];
            const int r0 = mbase + mf * 16;
            const int c0 = nbase + nf * 8;
            if (EPI == 2) {
                const int2 m0 = *(const int2*)(mask + (size_t)r0 * N + c0);
                const int2 m1 = *(const int2*)(mask + (size_t)(r0 + 8) * N + c0);
                float2 o0, o1;
                o0.x = m0.x ? c[0] * scale : NEG_INF;
                o0.y = m0.y ? c[1] * scale : NEG_INF;
                o1.x = m1.x ? c[2] * scale : NEG_INF;
                o1.y = m1.y ? c[3] * scale : NEG_INF;
                *(float2*)(outF + bz * sC + (size_t)r0 * N + c0)       = o0;
                *(float2*)(outF + bz * sC + (size_t)(r0 + 8) * N + c0) = o1;
            } else if (EPI == 3) {
                float2 o0 = make_float2(c[0], c[1]);
                float2 o1 = make_float2(c[2], c[3]);
                *(float2*)(outF + bz * sC + (size_t)r0 * N + c0)       = o0;
                *(float2*)(outF + bz * sC + (size_t)(r0 + 8) * N + c0) = o1;
            } else if (EPI == 0) {
                unsigned short h0, l0, h1, l1;
                bsplit(c[0], h0, l0);
                bsplit(c[1], h1, l1);
                outHi[((size_t)r0 * N + c0) >> 1] = (unsigned)h0 | ((unsigned)h1 << 16);
                outLo[((size_t)r0 * N + c0) >> 1] = (unsigned)l0 | ((unsigned)l1 << 16);
                bsplit(c[2], h0, l0);
                bsplit(c[3], h1, l1);
                outHi[((size_t)(r0 + 8) * N + c0) >> 1] = (unsigned)h0 | ((unsigned)h1 << 16);
                outLo[((size_t)(r0 + 8) * N + c0) >> 1] = (unsigned)l0 | ((unsigned)l1 << 16);
            } else {  // EPI == 1: VT[b][o][t]
                #pragma unroll
                for (int e = 0; e < 4; ++e) {
                    const int r = r0 + (e >> 1) * 8;
                    const int o = c0 + (e & 1);
                    unsigned short h, l;
                    bsplit(c[e], h, l);
                    const size_t idx = (((size_t)(r >> 11)) * E_ + o) * T_ + (r & (T_ - 1));
                    outTHi[idx] = h;
                    outTLo[idx] = l;
                }
            }
        }
    }
}

// ---------------- softmax: fp32 S row -> split bf16 P ----------------
__global__ void softmax_split_kernel(const float* __restrict__ S,
                                     uint4* __restrict__ Phi, uint4* __restrict__ Plo)
{
    const int row = blockIdx.x, tid = threadIdx.x;
    const float4* src = (const float4*)(S + (size_t)row * T_);
    float4 a = src[tid * 2], b2 = src[tid * 2 + 1];
    float v[8] = {a.x, a.y, a.z, a.w, b2.x, b2.y, b2.z, b2.w};

    float mx = v[0];
    #pragma unroll
    for (int i = 1; i < 8; ++i) mx = fmaxf(mx, v[i]);
    __shared__ float red[8];
    #pragma unroll
    for (int o = 16; o > 0; o >>= 1) mx = fmaxf(mx, __shfl_xor_sync(0xffffffff, mx, o));
    if ((tid & 31) == 0) red[tid >> 5] = mx;
    __syncthreads();
    float rmax = fmaxf(fmaxf(fmaxf(red[0], red[1]), fmaxf(red[2], red[3])),
                       fmaxf(fmaxf(red[4], red[5]), fmaxf(red[6], red[7])));
    __syncthreads();

    float sum = 0.0f;
    #pragma unroll
    for (int i = 0; i < 8; ++i) { v[i] = expf(v[i] - rmax); sum += v[i]; }
    #pragma unroll
    for (int o = 16; o > 0; o >>= 1) sum += __shfl_xor_sync(0xffffffff, sum, o);
    if ((tid & 31) == 0) red[tid >> 5] = sum;
    __syncthreads();
    float tot = red[0] + red[1] + red[2] + red[3] + red[4] + red[5] + red[6] + red[7];
    float inv = 1.0f / tot;

    unsigned hw[4], lw[4];
    #pragma unroll
    for (int j = 0; j < 4; ++j) {
        unsigned short h0, l0, h1, l1;
        bsplit(v[2 * j] * inv, h0, l0);
        bsplit(v[2 * j + 1] * inv, h1, l1);
        hw[j] = (unsigned)h0 | ((unsigned)h1 << 16);
        lw[j] = (unsigned)l0 | ((unsigned)l1 << 16);
    }
    Phi[(size_t)row * (T_ / 8) + tid] = make_uint4(hw[0], hw[1], hw[2], hw[3]);
    Plo[(size_t)row * (T_ / 8) + tid] = make_uint4(lw[0], lw[1], lw[2], lw[3]);
}

// ---------------- driver ----------------
extern "C" void kernel_launch(void* const* d_in, const int* in_sizes, int n_in,
                              void* d_out, int out_size)
{
    const float* q    = (const float*)d_in[0];
    const float* k    = (const float*)d_in[1];
    const float* v    = (const float*)d_in[2];
    const int*   mask = (const int*)  d_in[3];
    const float* Wq   = (const float*)d_in[4];
    const float* Wk   = (const float*)d_in[5];
    const float* Wv   = (const float*)d_in[6];
    float* out = (float*)d_out;

    unsigned short *qhi, *qlo, *khi, *klo, *vhi, *vlo;
    unsigned short *Wqhi, *Wqlo, *Wkhi, *Wklo, *Wvhi, *Wvlo;
    unsigned short *Qhi, *Qlo, *Khi, *Klo, *VThi, *VTlo, *Phi, *Plo;
    float* S;
    cudaGetSymbolAddress((void**)&qhi,  g_qhi);
    cudaGetSymbolAddress((void**)&qlo,  g_qlo);
    cudaGetSymbolAddress((void**)&khi,  g_khi);
    cudaGetSymbolAddress((void**)&klo,  g_klo);
    cudaGetSymbolAddress((void**)&vhi,  g_vhi);
    cudaGetSymbolAddress((void**)&vlo,  g_vlo);
    cudaGetSymbolAddress((void**)&Wqhi, g_Wqhi);
    cudaGetSymbolAddress((void**)&Wqlo, g_Wqlo);
    cudaGetSymbolAddress((void**)&Wkhi, g_Wkhi);
    cudaGetSymbolAddress((void**)&Wklo, g_Wklo);
    cudaGetSymbolAddress((void**)&Wvhi, g_Wvhi);
    cudaGetSymbolAddress((void**)&Wvlo, g_Wvlo);
    cudaGetSymbolAddress((void**)&Qhi,  g_Qhi);
    cudaGetSymbolAddress((void**)&Qlo,  g_Qlo);
    cudaGetSymbolAddress((void**)&Khi,  g_Khi);
    cudaGetSymbolAddress((void**)&Klo,  g_Klo);
    cudaGetSymbolAddress((void**)&VThi, g_VThi);
    cudaGetSymbolAddress((void**)&VTlo, g_VTlo);
    cudaGetSymbolAddress((void**)&S,    g_S);
    cudaGetSymbolAddress((void**)&Phi,  g_Phi);
    cudaGetSymbolAddress((void**)&Plo,  g_Plo);

    cudaFuncSetAttribute(gemm_mma<0>, cudaFuncAttributeMaxDynamicSharedMemorySize, SMEM_BYTES);
    cudaFuncSetAttribute(gemm_mma<1>, cudaFuncAttributeMaxDynamicSharedMemorySize, SMEM_BYTES);
    cudaFuncSetAttribute(gemm_mma<2>, cudaFuncAttributeMaxDynamicSharedMemorySize, SMEM_BYTES);
    cudaFuncSetAttribute(gemm_mma<3>, cudaFuncAttributeMaxDynamicSharedMemorySize, SMEM_BYTES);

    const int nx = B_ * T_ * E_ / 4;
    const int nw = E_ * E_ / 4;
    split_kernel<<<(nx + 255) / 256, 256>>>((const float4*)q,  (uint2*)qhi,  (uint2*)qlo,  nx);
    split_kernel<<<(nx + 255) / 256, 256>>>((const float4*)k,  (uint2*)khi,  (uint2*)klo,  nx);
    split_kernel<<<(nx + 255) / 256, 256>>>((const float4*)v,  (uint2*)vhi,  (uint2*)vlo,  nx);
    split_kernel<<<(nw + 255) / 256, 256>>>((const float4*)Wq, (uint2*)Wqhi, (uint2*)Wqlo, nw);
    split_kernel<<<(nw + 255) / 256, 256>>>((const float4*)Wk, (uint2*)Wkhi, (uint2*)Wklo, nw);
    split_kernel<<<(nw + 255) / 256, 256>>>((const float4*)Wv, (uint2*)Wvhi, (uint2*)Wvlo, nw);

    // projections: [B*T, E] = [B*T, E] x [E, E]^T
    dim3 gp(E_ / 256, (B_ * T_) / 128, 1);
    gemm_mma<0><<<gp, 256, SMEM_BYTES>>>(qhi, qlo, Wqhi, Wqlo,
        nullptr, (unsigned*)Qhi, (unsigned*)Qlo, nullptr, nullptr,
        E_, E_, 0, 0, 0, nullptr, 0.f);
    gemm_mma<0><<<gp, 256, SMEM_BYTES>>>(khi, klo, Wkhi, Wklo,
        nullptr, (unsigned*)Khi, (unsigned*)Klo, nullptr, nullptr,
        E_, E_, 0, 0, 0, nullptr, 0.f);
    gemm_mma<1><<<gp, 256, SMEM_BYTES>>>(vhi, vlo, Wvhi, Wvlo,
        nullptr, nullptr, nullptr, VThi, VTlo,
        E_, E_, 0, 0, 0, nullptr, 0.f);

    // scores: per batch [T,T] = Q x K^T, scaled + masked
    dim3 gs(T_ / 256, T_ / 128, B_);
    gemm_mma<2><<<gs, 256, SMEM_BYTES>>>(Qhi, Qlo, Khi, Klo,
        S, nullptr, nullptr, nullptr, nullptr,
        T_, E_, (size_t)T_ * E_, (size_t)T_ * E_, (size_t)T_ * T_, mask, 0.03125f);

    softmax_split_kernel<<<B_ * T_, 256>>>(S, (uint4*)Phi, (uint4*)Plo);

    // out: per batch [T,E] = P x VT^T  (VT stored [o][t])
    dim3 gv(E_ / 256, T_ / 128, B_);
    gemm_mma<3><<<gv, 256, SMEM_BYTES>>>(Phi, Plo, VThi, VTlo,
        out, nullptr, nullptr, nullptr, nullptr,
        E_, T_, (size_t)T_ * T_, (size_t)E_ * T_, (size_t)T_ * E_, nullptr, 1.f);
}

// round 10
// speedup vs baseline: 2.3885x; 1.4759x over previous
#include <cuda_runtime.h>
#include <cuda_fp16.h>
#include <stdint.h>
#include <math.h>

#define B_ 8
#define T_ 2048
#define E_ 1024

// ---- GEMM tiling: CTA 128M x 256N, 8 warps (2x4), warp tile 64x64, BK=32 ----
// fp16 2-pass: A = hi+lo, B = hi only.
#define NSTAGE 3
#define ROWB 80              // smem row stride bytes (64B data + 16 pad; conflict-free ldmatrix)
#define A_HI 0
#define A_LO 10240           // 128 * 80
#define B_HI 20480
#define STG_B 40960          // + 256 * 80
#define SMEM_BYTES (NSTAGE * STG_B)   // 122880

// ---------------- device scratch (allocation-free rule) ----------------
__device__ __align__(16) unsigned short g_qhi[(size_t)B_*T_*E_];
__device__ __align__(16) unsigned short g_qlo[(size_t)B_*T_*E_];
__device__ __align__(16) unsigned short g_khi[(size_t)B_*T_*E_];
__device__ __align__(16) unsigned short g_klo[(size_t)B_*T_*E_];
__device__ __align__(16) unsigned short g_vhi[(size_t)B_*T_*E_];
__device__ __align__(16) unsigned short g_vlo[(size_t)B_*T_*E_];
__device__ __align__(16) unsigned short g_Wq [(size_t)E_*E_];
__device__ __align__(16) unsigned short g_Wk [(size_t)E_*E_];
__device__ __align__(16) unsigned short g_Wv [(size_t)E_*E_];
__device__ __align__(16) unsigned short g_Qhi[(size_t)B_*T_*E_];
__device__ __align__(16) unsigned short g_Qlo[(size_t)B_*T_*E_];
__device__ __align__(16) unsigned short g_Khi[(size_t)B_*T_*E_];
__device__ __align__(16) unsigned short g_VThi[(size_t)B_*E_*T_];  // [b][o][t]
__device__ __align__(16) float          g_S   [(size_t)B_*T_*T_];
__device__ __align__(16) unsigned short g_Phi [(size_t)B_*T_*T_];
__device__ __align__(16) unsigned short g_Plo [(size_t)B_*T_*T_];

// ---------------- helpers ----------------
__device__ __forceinline__ uint32_t smem_u32(const void* p) {
    uint32_t a;
    asm("{ .reg .u64 t; cvta.to.shared.u64 t, %1; cvt.u32.u64 %0, t; }" : "=r"(a) : "l"(p));
    return a;
}
__device__ __forceinline__ void cpasync16(uint32_t dst, const void* src) {
    asm volatile("cp.async.cg.shared.global [%0], [%1], 16;" :: "r"(dst), "l"(src) : "memory");
}
__device__ __forceinline__ void ldsm4(unsigned* r, uint32_t addr) {
    asm volatile("ldmatrix.sync.aligned.m8n8.x4.shared.b16 {%0,%1,%2,%3}, [%4];"
                 : "=r"(r[0]), "=r"(r[1]), "=r"(r[2]), "=r"(r[3]) : "r"(addr));
}
__device__ __forceinline__ void mma16816(float* c, const unsigned* a,
                                         unsigned b0, unsigned b1) {
    asm volatile(
        "mma.sync.aligned.m16n8k16.row.col.f32.f16.f16.f32 "
        "{%0,%1,%2,%3}, {%4,%5,%6,%7}, {%8,%9}, {%0,%1,%2,%3};"
        : "+f"(c[0]), "+f"(c[1]), "+f"(c[2]), "+f"(c[3])
        : "r"(a[0]), "r"(a[1]), "r"(a[2]), "r"(a[3]), "r"(b0), "r"(b1));
}
__device__ __forceinline__ void hsplit(float x, unsigned short& h, unsigned short& l) {
    __half hh = __float2half_rn(x);
    float r = x - __half2float(hh);
    __half ll = __float2half_rn(r);
    h = __half_as_ushort(hh);
    l = __half_as_ushort(ll);
}
__device__ __forceinline__ unsigned short hcvt(float x) {
    return __half_as_ushort(__float2half_rn(x));
}

// ---------------- split fp32 -> (hi, lo) fp16 arrays ----------------
__global__ void split_kernel(const float4* __restrict__ x,
                             uint2* __restrict__ hi, uint2* __restrict__ lo, int n4)
{
    int i = blockIdx.x * blockDim.x + threadIdx.x;
    if (i >= n4) return;
    float4 v = x[i];
    float vv[4] = {v.x, v.y, v.z, v.w};
    unsigned short h[4], l[4];
    #pragma unroll
    for (int j = 0; j < 4; ++j) hsplit(vv[j], h[j], l[j]);
    uint2 hv, lv;
    hv.x = (unsigned)h[0] | ((unsigned)h[1] << 16);
    hv.y = (unsigned)h[2] | ((unsigned)h[3] << 16);
    lv.x = (unsigned)l[0] | ((unsigned)l[1] << 16);
    lv.y = (unsigned)l[2] | ((unsigned)l[3] << 16);
    hi[i] = hv;
    lo[i] = lv;
}

// ---------------- convert fp32 -> fp16 (hi only, for B-side operands) --------
__global__ void tohalf_kernel(const float4* __restrict__ x, uint2* __restrict__ hi, int n4)
{
    int i = blockIdx.x * blockDim.x + threadIdx.x;
    if (i >= n4) return;
    float4 v = x[i];
    uint2 hv;
    hv.x = (unsigned)hcvt(v.x) | ((unsigned)hcvt(v.y) << 16);
    hv.y = (unsigned)hcvt(v.z) | ((unsigned)hcvt(v.w) << 16);
    hi[i] = hv;
}

// ---------------- cp.async stage fill ----------------
// A: 128 rows x 32 K (hi+lo), B: 256 rows x 32 K (hi only). Row = 64B = 4 chunks.
__device__ __forceinline__ void fill_stage(uint32_t sb,
    const unsigned short* __restrict__ Ah, const unsigned short* __restrict__ Al,
    const unsigned short* __restrict__ Bh, int K, int tid)
{
    #pragma unroll
    for (int i = 0; i < 2; ++i) {                       // A: 512 chunks, hi+lo
        const int idx = (i << 8) + tid;
        const int row = idx >> 2, ch = idx & 3;
        const size_t off = (size_t)row * K + ch * 8;
        const uint32_t d = sb + row * ROWB + ch * 16;
        cpasync16(d + A_HI, Ah + off);
        cpasync16(d + A_LO, Al + off);
    }
    #pragma unroll
    for (int i = 0; i < 4; ++i) {                       // B: 1024 chunks, hi only
        const int idx = (i << 8) + tid;
        const int row = idx >> 2, ch = idx & 3;
        const size_t off = (size_t)row * K + ch * 8;
        cpasync16(sb + B_HI + row * ROWB + ch * 16, Bh + off);
    }
}

// ---------------- fp16 2-pass NT GEMM (mma.sync path) ----------------
// C[m,n] = sum_k A[m,k]*B[n,k]; acc = Ahi*Bhi + Alo*Bhi (fp32 acc).
// EPI=0: hi+lo fp16 out ([M,N])      EPI=4: hi-only fp16 out ([M,N])
// EPI=1: transposed hi fp16 out [b][n][t]
// EPI=2: v*scale, mask==0 -> -inf, fp32 out   EPI=3: fp32 out
template<int EPI>
__global__ __launch_bounds__(256, 1)
void gemm_mma(const unsigned short* __restrict__ Ahi, const unsigned short* __restrict__ Alo,
              const unsigned short* __restrict__ Bhi,
              float* __restrict__ outF, unsigned* __restrict__ outHi,
              unsigned* __restrict__ outLo, unsigned short* __restrict__ outTHi,
              int N, int K, size_t sA, size_t sB, size_t sC,
              const int* __restrict__ mask, float scale)
{
    extern __shared__ char smem[];
    const uint32_t smb = smem_u32(smem);
    const int tid = threadIdx.x, lane = tid & 31, wid = tid >> 5;
    const int wm = wid & 1, wn = wid >> 1;          // 2 x 4 warp grid, warp tile 64x64
    const int mblk = blockIdx.y << 7, nblk = blockIdx.x << 8;
    const size_t bz = blockIdx.z;

    const unsigned short* pAh = Ahi + bz * sA + (size_t)mblk * K;
    const unsigned short* pAl = Alo + bz * sA + (size_t)mblk * K;
    const unsigned short* pBh = Bhi + bz * sB + (size_t)nblk * K;

    float acc[4][8][4];
    #pragma unroll
    for (int i = 0; i < 4; ++i)
        #pragma unroll
        for (int j = 0; j < 8; ++j)
            #pragma unroll
            for (int e = 0; e < 4; ++e) acc[i][j][e] = 0.0f;

    const int nk = K >> 5;

    #pragma unroll
    for (int s = 0; s < NSTAGE - 1; ++s) {
        fill_stage(smb + s * STG_B, pAh + s * 32, pAl + s * 32, pBh + s * 32, K, tid);
        asm volatile("cp.async.commit_group;" ::: "memory");
    }

    const int lrow = lane & 15;
    const uint32_t lcoff = (lane >> 4) << 4;   // 0 or 16 bytes

    for (int kt = 0; kt < nk; ++kt) {
        asm volatile("cp.async.wait_group 1;" ::: "memory");
        __syncthreads();

        const int s2 = kt + NSTAGE - 1;
        if (s2 < nk) {
            fill_stage(smb + (s2 % NSTAGE) * STG_B,
                       pAh + s2 * 32, pAl + s2 * 32, pBh + s2 * 32, K, tid);
        }
        asm volatile("cp.async.commit_group;" ::: "memory");

        const uint32_t sb = smb + (kt % NSTAGE) * STG_B;
        #pragma unroll
        for (int ks = 0; ks < 2; ++ks) {
            const uint32_t koff = (ks << 5) + lcoff;
            unsigned ah[4][4], al[4][4], bh[4][4];
            #pragma unroll
            for (int mf = 0; mf < 4; ++mf) {
                uint32_t r = sb + (uint32_t)(wm * 64 + mf * 16 + lrow) * ROWB + koff;
                ldsm4(ah[mf], r + A_HI);
                ldsm4(al[mf], r + A_LO);
            }
            #pragma unroll
            for (int nf2 = 0; nf2 < 4; ++nf2) {
                uint32_t r = sb + (uint32_t)(wn * 64 + nf2 * 16 + lrow) * ROWB + koff;
                ldsm4(bh[nf2], r + B_HI);
            }
            #pragma unroll
            for (int mf = 0; mf < 4; ++mf) {
                #pragma unroll
                for (int nf = 0; nf < 8; ++nf) {
                    const int g = nf >> 1, s = nf & 1;
                    mma16816(acc[mf][nf], ah[mf], bh[g][s], bh[g][s + 2]);
                    mma16816(acc[mf][nf], al[mf], bh[g][s], bh[g][s + 2]);
                }
            }
        }
    }

    // ---------------- epilogue ----------------
    const float NEG_INF = __int_as_float(0xff800000);
    const int mbase = mblk + wm * 64 + (lane >> 2);
    const int nbase = nblk + wn * 64 + ((lane & 3) << 1);
    #pragma unroll
    for (int mf = 0; mf < 4; ++mf) {
        #pragma unroll
        for (int nf = 0; nf < 8; ++nf) {
            const float* c = acc[mf][nf];
            const int r0 = mbase + mf * 16;
            const int c0 = nbase + nf * 8;
            if (EPI == 2) {
                const int2 m0 = *(const int2*)(mask + (size_t)r0 * N + c0);
                const int2 m1 = *(const int2*)(mask + (size_t)(r0 + 8) * N + c0);
                float2 o0, o1;
                o0.x = m0.x ? c[0] * scale : NEG_INF;
                o0.y = m0.y ? c[1] * scale : NEG_INF;
                o1.x = m1.x ? c[2] * scale : NEG_INF;
                o1.y = m1.y ? c[3] * scale : NEG_INF;
                *(float2*)(outF + bz * sC + (size_t)r0 * N + c0)       = o0;
                *(float2*)(outF + bz * sC + (size_t)(r0 + 8) * N + c0) = o1;
            } else if (EPI == 3) {
                *(float2*)(outF + bz * sC + (size_t)r0 * N + c0)       = make_float2(c[0], c[1]);
                *(float2*)(outF + bz * sC + (size_t)(r0 + 8) * N + c0) = make_float2(c[2], c[3]);
            } else if (EPI == 0) {
                unsigned short h0, l0, h1, l1;
                hsplit(c[0], h0, l0);
                hsplit(c[1], h1, l1);
                outHi[((size_t)r0 * N + c0) >> 1] = (unsigned)h0 | ((unsigned)h1 << 16);
                outLo[((size_t)r0 * N + c0) >> 1] = (unsigned)l0 | ((unsigned)l1 << 16);
                hsplit(c[2], h0, l0);
                hsplit(c[3], h1, l1);
                outHi[((size_t)(r0 + 8) * N + c0) >> 1] = (unsigned)h0 | ((unsigned)h1 << 16);
                outLo[((size_t)(r0 + 8) * N + c0) >> 1] = (unsigned)l0 | ((unsigned)l1 << 16);
            } else if (EPI == 4) {
                outHi[((size_t)r0 * N + c0) >> 1] =
                    (unsigned)hcvt(c[0]) | ((unsigned)hcvt(c[1]) << 16);
                outHi[((size_t)(r0 + 8) * N + c0) >> 1] =
                    (unsigned)hcvt(c[2]) | ((unsigned)hcvt(c[3]) << 16);
            } else {  // EPI == 1: VT[b][o][t], hi only
                #pragma unroll
                for (int e = 0; e < 4; ++e) {
                    const int r = r0 + (e >> 1) * 8;
                    const int o = c0 + (e & 1);
                    const size_t idx = (((size_t)(r >> 11)) * E_ + o) * T_ + (r & (T_ - 1));
                    outTHi[idx] = hcvt(c[e]);
                }
            }
        }
    }
}

// ---------------- softmax: fp32 S row -> split fp16 P ----------------
__global__ void softmax_split_kernel(const float* __restrict__ S,
                                     uint4* __restrict__ Phi, uint4* __restrict__ Plo)
{
    const int row = blockIdx.x, tid = threadIdx.x;
    const float4* src = (const float4*)(S + (size_t)row * T_);
    float4 a = src[tid * 2], b2 = src[tid * 2 + 1];
    float v[8] = {a.x, a.y, a.z, a.w, b2.x, b2.y, b2.z, b2.w};

    float mx = v[0];
    #pragma unroll
    for (int i = 1; i < 8; ++i) mx = fmaxf(mx, v[i]);
    __shared__ float red[8];
    #pragma unroll
    for (int o = 16; o > 0; o >>= 1) mx = fmaxf(mx, __shfl_xor_sync(0xffffffff, mx, o));
    if ((tid & 31) == 0) red[tid >> 5] = mx;
    __syncthreads();
    float rmax = fmaxf(fmaxf(fmaxf(red[0], red[1]), fmaxf(red[2], red[3])),
                       fmaxf(fmaxf(red[4], red[5]), fmaxf(red[6], red[7])));
    __syncthreads();

    float sum = 0.0f;
    #pragma unroll
    for (int i = 0; i < 8; ++i) { v[i] = expf(v[i] - rmax); sum += v[i]; }
    #pragma unroll
    for (int o = 16; o > 0; o >>= 1) sum += __shfl_xor_sync(0xffffffff, sum, o);
    if ((tid & 31) == 0) red[tid >> 5] = sum;
    __syncthreads();
    float tot = red[0] + red[1] + red[2] + red[3] + red[4] + red[5] + red[6] + red[7];
    float inv = 1.0f / tot;

    unsigned hw[4], lw[4];
    #pragma unroll
    for (int j = 0; j < 4; ++j) {
        unsigned short h0, l0, h1, l1;
        hsplit(v[2 * j] * inv, h0, l0);
        hsplit(v[2 * j + 1] * inv, h1, l1);
        hw[j] = (unsigned)h0 | ((unsigned)h1 << 16);
        lw[j] = (unsigned)l0 | ((unsigned)l1 << 16);
    }
    Phi[(size_t)row * (T_ / 8) + tid] = make_uint4(hw[0], hw[1], hw[2], hw[3]);
    Plo[(size_t)row * (T_ / 8) + tid] = make_uint4(lw[0], lw[1], lw[2], lw[3]);
}

// ---------------- driver ----------------
extern "C" void kernel_launch(void* const* d_in, const int* in_sizes, int n_in,
                              void* d_out, int out_size)
{
    const float* q    = (const float*)d_in[0];
    const float* k    = (const float*)d_in[1];
    const float* v    = (const float*)d_in[2];
    const int*   mask = (const int*)  d_in[3];
    const float* Wq   = (const float*)d_in[4];
    const float* Wk   = (const float*)d_in[5];
    const float* Wv   = (const float*)d_in[6];
    float* out = (float*)d_out;

    unsigned short *qhi, *qlo, *khi, *klo, *vhi, *vlo;
    unsigned short *Wqh, *Wkh, *Wvh;
    unsigned short *Qhi, *Qlo, *Khi, *VThi, *Phi, *Plo;
    float* S;
    cudaGetSymbolAddress((void**)&qhi,  g_qhi);
    cudaGetSymbolAddress((void**)&qlo,  g_qlo);
    cudaGetSymbolAddress((void**)&khi,  g_khi);
    cudaGetSymbolAddress((void**)&klo,  g_klo);
    cudaGetSymbolAddress((void**)&vhi,  g_vhi);
    cudaGetSymbolAddress((void**)&vlo,  g_vlo);
    cudaGetSymbolAddress((void**)&Wqh,  g_Wq);
    cudaGetSymbolAddress((void**)&Wkh,  g_Wk);
    cudaGetSymbolAddress((void**)&Wvh,  g_Wv);
    cudaGetSymbolAddress((void**)&Qhi,  g_Qhi);
    cudaGetSymbolAddress((void**)&Qlo,  g_Qlo);
    cudaGetSymbolAddress((void**)&Khi,  g_Khi);
    cudaGetSymbolAddress((void**)&VThi, g_VThi);
    cudaGetSymbolAddress((void**)&S,    g_S);
    cudaGetSymbolAddress((void**)&Phi,  g_Phi);
    cudaGetSymbolAddress((void**)&Plo,  g_Plo);

    cudaFuncSetAttribute(gemm_mma<0>, cudaFuncAttributeMaxDynamicSharedMemorySize, SMEM_BYTES);
    cudaFuncSetAttribute(gemm_mma<1>, cudaFuncAttributeMaxDynamicSharedMemorySize, SMEM_BYTES);
    cudaFuncSetAttribute(gemm_mma<2>, cudaFuncAttributeMaxDynamicSharedMemorySize, SMEM_BYTES);
    cudaFuncSetAttribute(gemm_mma<3>, cudaFuncAttributeMaxDynamicSharedMemorySize, SMEM_BYTES);
    cudaFuncSetAttribute(gemm_mma<4>, cudaFuncAttributeMaxDynamicSharedMemorySize, SMEM_BYTES);

    const int nx = B_ * T_ * E_ / 4;
    const int nw = E_ * E_ / 4;
    split_kernel<<<(nx + 255) / 256, 256>>>((const float4*)q, (uint2*)qhi, (uint2*)qlo, nx);
    split_kernel<<<(nx + 255) / 256, 256>>>((const float4*)k, (uint2*)khi, (uint2*)klo, nx);
    split_kernel<<<(nx + 255) / 256, 256>>>((const float4*)v, (uint2*)vhi, (uint2*)vlo, nx);
    tohalf_kernel<<<(nw + 255) / 256, 256>>>((const float4*)Wq, (uint2*)Wqh, nw);
    tohalf_kernel<<<(nw + 255) / 256, 256>>>((const float4*)Wk, (uint2*)Wkh, nw);
    tohalf_kernel<<<(nw + 255) / 256, 256>>>((const float4*)Wv, (uint2*)Wvh, nw);

    // projections: [B*T, E] = [B*T, E] x [E, E]^T
    dim3 gp(E_ / 256, (B_ * T_) / 128, 1);
    gemm_mma<0><<<gp, 256, SMEM_BYTES>>>(qhi, qlo, Wqh,
        nullptr, (unsigned*)Qhi, (unsigned*)Qlo, nullptr,
        E_, E_, 0, 0, 0, nullptr, 0.f);
    gemm_mma<4><<<gp, 256, SMEM_BYTES>>>(khi, klo, Wkh,
        nullptr, (unsigned*)Khi, nullptr, nullptr,
        E_, E_, 0, 0, 0, nullptr, 0.f);
    gemm_mma<1><<<gp, 256, SMEM_BYTES>>>(vhi, vlo, Wvh,
        nullptr, nullptr, nullptr, VThi,
        E_, E_, 0, 0, 0, nullptr, 0.f);

    // scores: per batch [T,T] = Q x K^T, scaled + masked
    dim3 gs(T_ / 256, T_ / 128, B_);
    gemm_mma<2><<<gs, 256, SMEM_BYTES>>>(Qhi, Qlo, Khi,
        S, nullptr, nullptr, nullptr,
        T_, E_, (size_t)T_ * E_, (size_t)T_ * E_, (size_t)T_ * T_, mask, 0.03125f);

    softmax_split_kernel<<<B_ * T_, 256>>>(S, (uint4*)Phi, (uint4*)Plo);

    // out: per batch [T,E] = P x VT^T  (VT stored [o][t])
    dim3 gv(E_ / 256, T_ / 128, B_);
    gemm_mma<3><<<gv, 256, SMEM_BYTES>>>(Phi, Plo, VThi,
        out, nullptr, nullptr, nullptr,
        E_, T_, (size_t)T_ * T_, (size_t)E_ * T_, (size_t)T_ * E_, nullptr, 1.f);
}

// round 11
// speedup vs baseline: 2.8655x; 1.1997x over previous
#include <cuda_runtime.h>
#include <cuda_fp16.h>
#include <stdint.h>
#include <math.h>

#define B_ 8
#define T_ 2048
#define E_ 1024

// ---- GEMM tiling: CTA 128M x 256N, 8 warps (2x4), warp tile 64x64, BK=32 ----
// PASSES=2: A = hi+lo fp16, 2 mma passes. PASSES=1: A = hi only. B = hi only always.
#define NSTAGE 3
#define ROWB 80              // smem row stride bytes (64B data + 16 pad; conflict-free ldmatrix)
#define A_HI 0
#define A_LO 10240           // 128 * 80
#define B_HI 20480
#define STG_B 40960          // + 256 * 80
#define SMEM_BYTES (NSTAGE * STG_B)   // 122880

// ---------------- device scratch (allocation-free rule) ----------------
__device__ __align__(16) unsigned short g_qh [(size_t)B_*T_*E_];
__device__ __align__(16) unsigned short g_kh [(size_t)B_*T_*E_];
__device__ __align__(16) unsigned short g_vh [(size_t)B_*T_*E_];
__device__ __align__(16) unsigned short g_Wq [(size_t)E_*E_];
__device__ __align__(16) unsigned short g_Wk [(size_t)E_*E_];
__device__ __align__(16) unsigned short g_Wv [(size_t)E_*E_];
__device__ __align__(16) unsigned short g_Qhi[(size_t)B_*T_*E_];
__device__ __align__(16) unsigned short g_Qlo[(size_t)B_*T_*E_];
__device__ __align__(16) unsigned short g_Khi[(size_t)B_*T_*E_];
__device__ __align__(16) unsigned short g_VThi[(size_t)B_*E_*T_];  // [b][o][t]
__device__ __align__(16) float          g_S   [(size_t)B_*T_*T_];
__device__ __align__(16) unsigned short g_Phi [(size_t)B_*T_*T_];
__device__ __align__(16) unsigned short g_Plo [(size_t)B_*T_*T_];

// ---------------- helpers ----------------
__device__ __forceinline__ uint32_t smem_u32(const void* p) {
    uint32_t a;
    asm("{ .reg .u64 t; cvta.to.shared.u64 t, %1; cvt.u32.u64 %0, t; }" : "=r"(a) : "l"(p));
    return a;
}
__device__ __forceinline__ void cpasync16(uint32_t dst, const void* src) {
    asm volatile("cp.async.cg.shared.global [%0], [%1], 16;" :: "r"(dst), "l"(src) : "memory");
}
__device__ __forceinline__ void ldsm4(unsigned* r, uint32_t addr) {
    asm volatile("ldmatrix.sync.aligned.m8n8.x4.shared.b16 {%0,%1,%2,%3}, [%4];"
                 : "=r"(r[0]), "=r"(r[1]), "=r"(r[2]), "=r"(r[3]) : "r"(addr));
}
__device__ __forceinline__ void mma16816(float* c, const unsigned* a,
                                         unsigned b0, unsigned b1) {
    asm volatile(
        "mma.sync.aligned.m16n8k16.row.col.f32.f16.f16.f32 "
        "{%0,%1,%2,%3}, {%4,%5,%6,%7}, {%8,%9}, {%0,%1,%2,%3};"
        : "+f"(c[0]), "+f"(c[1]), "+f"(c[2]), "+f"(c[3])
        : "r"(a[0]), "r"(a[1]), "r"(a[2]), "r"(a[3]), "r"(b0), "r"(b1));
}
__device__ __forceinline__ void hsplit(float x, unsigned short& h, unsigned short& l) {
    __half hh = __float2half_rn(x);
    float r = x - __half2float(hh);
    __half ll = __float2half_rn(r);
    h = __half_as_ushort(hh);
    l = __half_as_ushort(ll);
}
__device__ __forceinline__ unsigned short hcvt(float x) {
    return __half_as_ushort(__float2half_rn(x));
}

// ---------------- convert fp32 -> fp16 (hi only) ----------------
__global__ void tohalf_kernel(const float4* __restrict__ x, uint2* __restrict__ hi, int n4)
{
    int i = blockIdx.x * blockDim.x + threadIdx.x;
    if (i >= n4) return;
    float4 v = x[i];
    uint2 hv;
    hv.x = (unsigned)hcvt(v.x) | ((unsigned)hcvt(v.y) << 16);
    hv.y = (unsigned)hcvt(v.z) | ((unsigned)hcvt(v.w) << 16);
    hi[i] = hv;
}

// ---------------- cp.async stage fill ----------------
// A: 128 rows x 32 K (hi [+lo if PASSES==2]), B: 256 rows x 32 K (hi). Row = 64B = 4 chunks.
template<int PASSES>
__device__ __forceinline__ void fill_stage(uint32_t sb,
    const unsigned short* __restrict__ Ah, const unsigned short* __restrict__ Al,
    const unsigned short* __restrict__ Bh, int K, int tid)
{
    #pragma unroll
    for (int i = 0; i < 2; ++i) {                       // A: 512 chunks
        const int idx = (i << 8) + tid;
        const int row = idx >> 2, ch = idx & 3;
        const size_t off = (size_t)row * K + ch * 8;
        const uint32_t d = sb + row * ROWB + ch * 16;
        cpasync16(d + A_HI, Ah + off);
        if (PASSES == 2) cpasync16(d + A_LO, Al + off);
    }
    #pragma unroll
    for (int i = 0; i < 4; ++i) {                       // B: 1024 chunks, hi only
        const int idx = (i << 8) + tid;
        const int row = idx >> 2, ch = idx & 3;
        const size_t off = (size_t)row * K + ch * 8;
        cpasync16(sb + B_HI + row * ROWB + ch * 16, Bh + off);
    }
}

// ---------------- fp16 NT GEMM (mma.sync path) ----------------
// C[m,n] = sum_k A[m,k]*B[n,k]; acc = Ahi*Bhi [+ Alo*Bhi if PASSES==2] (fp32 acc).
// EPI=0: hi+lo fp16 out ([M,N])      EPI=4: hi-only fp16 out ([M,N])
// EPI=1: transposed hi fp16 out [b][n][t]
// EPI=2: v*scale, mask==0 -> -inf, fp32 out   EPI=3: fp32 out
template<int EPI, int PASSES>
__global__ __launch_bounds__(256, 1)
void gemm_mma(const unsigned short* __restrict__ Ahi, const unsigned short* __restrict__ Alo,
              const unsigned short* __restrict__ Bhi,
              float* __restrict__ outF, unsigned* __restrict__ outHi,
              unsigned* __restrict__ outLo, unsigned short* __restrict__ outTHi,
              int N, int K, size_t sA, size_t sB, size_t sC,
              const int* __restrict__ mask, float scale)
{
    extern __shared__ char smem[];
    const uint32_t smb = smem_u32(smem);
    const int tid = threadIdx.x, lane = tid & 31, wid = tid >> 5;
    const int wm = wid & 1, wn = wid >> 1;          // 2 x 4 warp grid, warp tile 64x64
    const int mblk = blockIdx.y << 7, nblk = blockIdx.x << 8;
    const size_t bz = blockIdx.z;

    const unsigned short* pAh = Ahi + bz * sA + (size_t)mblk * K;
    const unsigned short* pAl = (PASSES == 2) ? (Alo + bz * sA + (size_t)mblk * K)
                                              : (const unsigned short*)0;
    const unsigned short* pBh = Bhi + bz * sB + (size_t)nblk * K;

    float acc[4][8][4];
    #pragma unroll
    for (int i = 0; i < 4; ++i)
        #pragma unroll
        for (int j = 0; j < 8; ++j)
            #pragma unroll
            for (int e = 0; e < 4; ++e) acc[i][j][e] = 0.0f;

    const int nk = K >> 5;

    #pragma unroll
    for (int s = 0; s < NSTAGE - 1; ++s) {
        fill_stage<PASSES>(smb + s * STG_B, pAh + s * 32,
                           (PASSES == 2) ? pAl + s * 32 : pAl, pBh + s * 32, K, tid);
        asm volatile("cp.async.commit_group;" ::: "memory");
    }

    const int lrow = lane & 15;
    const uint32_t lcoff = (lane >> 4) << 4;   // 0 or 16 bytes

    for (int kt = 0; kt < nk; ++kt) {
        asm volatile("cp.async.wait_group 1;" ::: "memory");
        __syncthreads();

        const int s2 = kt + NSTAGE - 1;
        if (s2 < nk) {
            fill_stage<PASSES>(smb + (s2 % NSTAGE) * STG_B, pAh + s2 * 32,
                               (PASSES == 2) ? pAl + s2 * 32 : pAl, pBh + s2 * 32, K, tid);
        }
        asm volatile("cp.async.commit_group;" ::: "memory");

        const uint32_t sb = smb + (kt % NSTAGE) * STG_B;
        #pragma unroll
        for (int ks = 0; ks < 2; ++ks) {
            const uint32_t koff = (ks << 5) + lcoff;
            unsigned ah[4][4], al[4][4], bh[4][4];
            #pragma unroll
            for (int mf = 0; mf < 4; ++mf) {
                uint32_t r = sb + (uint32_t)(wm * 64 + mf * 16 + lrow) * ROWB + koff;
                ldsm4(ah[mf], r + A_HI);
                if (PASSES == 2) ldsm4(al[mf], r + A_LO);
            }
            #pragma unroll
            for (int nf2 = 0; nf2 < 4; ++nf2) {
                uint32_t r = sb + (uint32_t)(wn * 64 + nf2 * 16 + lrow) * ROWB + koff;
                ldsm4(bh[nf2], r + B_HI);
            }
            #pragma unroll
            for (int mf = 0; mf < 4; ++mf) {
                #pragma unroll
                for (int nf = 0; nf < 8; ++nf) {
                    const int g = nf >> 1, s = nf & 1;
                    mma16816(acc[mf][nf], ah[mf], bh[g][s], bh[g][s + 2]);
                    if (PASSES == 2) mma16816(acc[mf][nf], al[mf], bh[g][s], bh[g][s + 2]);
                }
            }
        }
    }

    // ---------------- epilogue ----------------
    const float NEG_INF = __int_as_float(0xff800000);
    const int mbase = mblk + wm * 64 + (lane >> 2);
    const int nbase = nblk + wn * 64 + ((lane & 3) << 1);
    #pragma unroll
    for (int mf = 0; mf < 4; ++mf) {
        #pragma unroll
        for (int nf = 0; nf < 8; ++nf) {
            const float* c = acc[mf][nf];
            const int r0 = mbase + mf * 16;
            const int c0 = nbase + nf * 8;
            if (EPI == 2) {
                const int2 m0 = *(const int2*)(mask + (size_t)r0 * N + c0);
                const int2 m1 = *(const int2*)(mask + (size_t)(r0 + 8) * N + c0);
                float2 o0, o1;
                o0.x = m0.x ? c[0] * scale : NEG_INF;
                o0.y = m0.y ? c[1] * scale : NEG_INF;
                o1.x = m1.x ? c[2] * scale : NEG_INF;
                o1.y = m1.y ? c[3] * scale : NEG_INF;
                *(float2*)(outF + bz * sC + (size_t)r0 * N + c0)       = o0;
                *(float2*)(outF + bz * sC + (size_t)(r0 + 8) * N + c0) = o1;
            } else if (EPI == 3) {
                *(float2*)(outF + bz * sC + (size_t)r0 * N + c0)       = make_float2(c[0], c[1]);
                *(float2*)(outF + bz * sC + (size_t)(r0 + 8) * N + c0) = make_float2(c[2], c[3]);
            } else if (EPI == 0) {
                unsigned short h0, l0, h1, l1;
                hsplit(c[0], h0, l0);
                hsplit(c[1], h1, l1);
                outHi[((size_t)r0 * N + c0) >> 1] = (unsigned)h0 | ((unsigned)h1 << 16);
                outLo[((size_t)r0 * N + c0) >> 1] = (unsigned)l0 | ((unsigned)l1 << 16);
                hsplit(c[2], h0, l0);
                hsplit(c[3], h1, l1);
                outHi[((size_t)(r0 + 8) * N + c0) >> 1] = (unsigned)h0 | ((unsigned)h1 << 16);
                outLo[((size_t)(r0 + 8) * N + c0) >> 1] = (unsigned)l0 | ((unsigned)l1 << 16);
            } else if (EPI == 4) {
                outHi[((size_t)r0 * N + c0) >> 1] =
                    (unsigned)hcvt(c[0]) | ((unsigned)hcvt(c[1]) << 16);
                outHi[((size_t)(r0 + 8) * N + c0) >> 1] =
                    (unsigned)hcvt(c[2]) | ((unsigned)hcvt(c[3]) << 16);
            } else {  // EPI == 1: VT[b][o][t], hi only
                #pragma unroll
                for (int e = 0; e < 4; ++e) {
                    const int r = r0 + (e >> 1) * 8;
                    const int o = c0 + (e & 1);
                    const size_t idx = (((size_t)(r >> 11)) * E_ + o) * T_ + (r & (T_ - 1));
                    outTHi[idx] = hcvt(c[e]);
                }
            }
        }
    }
}

// ---------------- softmax: fp32 S row -> split fp16 P ----------------
__global__ void softmax_split_kernel(const float* __restrict__ S,
                                     uint4* __restrict__ Phi, uint4* __restrict__ Plo)
{
    const int row = blockIdx.x, tid = threadIdx.x;
    const float4* src = (const float4*)(S + (size_t)row * T_);
    float4 a = src[tid * 2], b2 = src[tid * 2 + 1];
    float v[8] = {a.x, a.y, a.z, a.w, b2.x, b2.y, b2.z, b2.w};

    float mx = v[0];
    #pragma unroll
    for (int i = 1; i < 8; ++i) mx = fmaxf(mx, v[i]);
    __shared__ float red[8];
    #pragma unroll
    for (int o = 16; o > 0; o >>= 1) mx = fmaxf(mx, __shfl_xor_sync(0xffffffff, mx, o));
    if ((tid & 31) == 0) red[tid >> 5] = mx;
    __syncthreads();
    float rmax = fmaxf(fmaxf(fmaxf(red[0], red[1]), fmaxf(red[2], red[3])),
                       fmaxf(fmaxf(red[4], red[5]), fmaxf(red[6], red[7])));
    __syncthreads();

    float sum = 0.0f;
    #pragma unroll
    for (int i = 0; i < 8; ++i) { v[i] = expf(v[i] - rmax); sum += v[i]; }
    #pragma unroll
    for (int o = 16; o > 0; o >>= 1) sum += __shfl_xor_sync(0xffffffff, sum, o);
    if ((tid & 31) == 0) red[tid >> 5] = sum;
    __syncthreads();
    float tot = red[0] + red[1] + red[2] + red[3] + red[4] + red[5] + red[6] + red[7];
    float inv = 1.0f / tot;

    unsigned hw[4], lw[4];
    #pragma unroll
    for (int j = 0; j < 4; ++j) {
        unsigned short h0, l0, h1, l1;
        hsplit(v[2 * j] * inv, h0, l0);
        hsplit(v[2 * j + 1] * inv, h1, l1);
        hw[j] = (unsigned)h0 | ((unsigned)h1 << 16);
        lw[j] = (unsigned)l0 | ((unsigned)l1 << 16);
    }
    Phi[(size_t)row * (T_ / 8) + tid] = make_uint4(hw[0], hw[1], hw[2], hw[3]);
    Plo[(size_t)row * (T_ / 8) + tid] = make_uint4(lw[0], lw[1], lw[2], lw[3]);
}

// ---------------- driver ----------------
extern "C" void kernel_launch(void* const* d_in, const int* in_sizes, int n_in,
                              void* d_out, int out_size)
{
    const float* q    = (const float*)d_in[0];
    const float* k    = (const float*)d_in[1];
    const float* v    = (const float*)d_in[2];
    const int*   mask = (const int*)  d_in[3];
    const float* Wq   = (const float*)d_in[4];
    const float* Wk   = (const float*)d_in[5];
    const float* Wv   = (const float*)d_in[6];
    float* out = (float*)d_out;

    unsigned short *qh, *kh, *vh, *Wqh, *Wkh, *Wvh;
    unsigned short *Qhi, *Qlo, *Khi, *VThi, *Phi, *Plo;
    float* S;
    cudaGetSymbolAddress((void**)&qh,   g_qh);
    cudaGetSymbolAddress((void**)&kh,   g_kh);
    cudaGetSymbolAddress((void**)&vh,   g_vh);
    cudaGetSymbolAddress((void**)&Wqh,  g_Wq);
    cudaGetSymbolAddress((void**)&Wkh,  g_Wk);
    cudaGetSymbolAddress((void**)&Wvh,  g_Wv);
    cudaGetSymbolAddress((void**)&Qhi,  g_Qhi);
    cudaGetSymbolAddress((void**)&Qlo,  g_Qlo);
    cudaGetSymbolAddress((void**)&Khi,  g_Khi);
    cudaGetSymbolAddress((void**)&VThi, g_VThi);
    cudaGetSymbolAddress((void**)&S,    g_S);
    cudaGetSymbolAddress((void**)&Phi,  g_Phi);
    cudaGetSymbolAddress((void**)&Plo,  g_Plo);

    cudaFuncSetAttribute(gemm_mma<0,1>, cudaFuncAttributeMaxDynamicSharedMemorySize, SMEM_BYTES);
    cudaFuncSetAttribute(gemm_mma<1,1>, cudaFuncAttributeMaxDynamicSharedMemorySize, SMEM_BYTES);
    cudaFuncSetAttribute(gemm_mma<4,1>, cudaFuncAttributeMaxDynamicSharedMemorySize, SMEM_BYTES);
    cudaFuncSetAttribute(gemm_mma<2,2>, cudaFuncAttributeMaxDynamicSharedMemorySize, SMEM_BYTES);
    cudaFuncSetAttribute(gemm_mma<3,2>, cudaFuncAttributeMaxDynamicSharedMemorySize, SMEM_BYTES);

    const int nx = B_ * T_ * E_ / 4;
    const int nw = E_ * E_ / 4;
    tohalf_kernel<<<(nx + 255) / 256, 256>>>((const float4*)q,  (uint2*)qh,  nx);
    tohalf_kernel<<<(nx + 255) / 256, 256>>>((const float4*)k,  (uint2*)kh,  nx);
    tohalf_kernel<<<(nx + 255) / 256, 256>>>((const float4*)v,  (uint2*)vh,  nx);
    tohalf_kernel<<<(nw + 255) / 256, 256>>>((const float4*)Wq, (uint2*)Wqh, nw);
    tohalf_kernel<<<(nw + 255) / 256, 256>>>((const float4*)Wk, (uint2*)Wkh, nw);
    tohalf_kernel<<<(nw + 255) / 256, 256>>>((const float4*)Wv, (uint2*)Wvh, nw);

    // projections (single-pass A): [B*T, E] = [B*T, E] x [E, E]^T
    dim3 gp(E_ / 256, (B_ * T_) / 128, 1);
    gemm_mma<0,1><<<gp, 256, SMEM_BYTES>>>(qh, nullptr, Wqh,
        nullptr, (unsigned*)Qhi, (unsigned*)Qlo, nullptr,
        E_, E_, 0, 0, 0, nullptr, 0.f);
    gemm_mma<4,1><<<gp, 256, SMEM_BYTES>>>(kh, nullptr, Wkh,
        nullptr, (unsigned*)Khi, nullptr, nullptr,
        E_, E_, 0, 0, 0, nullptr, 0.f);
    gemm_mma<1,1><<<gp, 256, SMEM_BYTES>>>(vh, nullptr, Wvh,
        nullptr, nullptr, nullptr, VThi,
        E_, E_, 0, 0, 0, nullptr, 0.f);

    // scores (2-pass A): per batch [T,T] = Q x K^T, scaled + masked
    dim3 gs(T_ / 256, T_ / 128, B_);
    gemm_mma<2,2><<<gs, 256, SMEM_BYTES>>>(Qhi, Qlo, Khi,
        S, nullptr, nullptr, nullptr,
        T_, E_, (size_t)T_ * E_, (size_t)T_ * E_, (size_t)T_ * T_, mask, 0.03125f);

    softmax_split_kernel<<<B_ * T_, 256>>>(S, (uint4*)Phi, (uint4*)Plo);

    // out (2-pass A): per batch [T,E] = P x VT^T  (VT stored [o][t])
    dim3 gv(E_ / 256, T_ / 128, B_);
    gemm_mma<3,2><<<gv, 256, SMEM_BYTES>>>(Phi, Plo, VThi,
        out, nullptr, nullptr, nullptr,
        E_, T_, (size_t)T_ * T_, (size_t)E_ * T_, (size_t)T_ * E_, nullptr, 1.f);
}

// round 15
// speedup vs baseline: 3.9325x; 1.3724x over previous
#include <cuda_runtime.h>
#include <cuda_fp16.h>
#include <stdint.h>
#include <math.h>

#define B_ 8
#define T_ 2048
#define E_ 1024

// ---- GEMM tiling: CTA 128M x 256N, 8 warps (2x4), warp tile 64x64, BK=32 ----
// Single-pass fp16: C = Ahi * Bhi, fp32 accumulate.
#define NSTAGE 3
#define ROWB 80              // smem row stride bytes (64B data + 16 pad; conflict-free ldmatrix)
#define A_HI 0
#define B_HI 10240           // 128 * 80
#define STG_B 30720          // + 256 * 80
#define SMEM_BYTES (NSTAGE * STG_B)   // 92160

// ---------------- device scratch (allocation-free rule) ----------------
__device__ __align__(16) unsigned short g_qh [(size_t)B_*T_*E_];
__device__ __align__(16) unsigned short g_kh [(size_t)B_*T_*E_];
__device__ __align__(16) unsigned short g_vh [(size_t)B_*T_*E_];
__device__ __align__(16) unsigned short g_Wq [(size_t)E_*E_];
__device__ __align__(16) unsigned short g_Wk [(size_t)E_*E_];
__device__ __align__(16) unsigned short g_Wv [(size_t)E_*E_];
__device__ __align__(16) unsigned short g_Qhi[(size_t)B_*T_*E_];
__device__ __align__(16) unsigned short g_Khi[(size_t)B_*T_*E_];
__device__ __align__(16) unsigned short g_VThi[(size_t)B_*E_*T_];  // [b][o][t]
__device__ __align__(16) float          g_S   [(size_t)B_*T_*T_];
__device__ __align__(16) unsigned short g_Phi [(size_t)B_*T_*T_];

// ---------------- helpers ----------------
__device__ __forceinline__ uint32_t smem_u32(const void* p) {
    uint32_t a;
    asm("{ .reg .u64 t; cvta.to.shared.u64 t, %1; cvt.u32.u64 %0, t; }" : "=r"(a) : "l"(p));
    return a;
}
__device__ __forceinline__ void cpasync16(uint32_t dst, const void* src) {
    asm volatile("cp.async.cg.shared.global [%0], [%1], 16;" :: "r"(dst), "l"(src) : "memory");
}
__device__ __forceinline__ void ldsm4(unsigned* r, uint32_t addr) {
    asm volatile("ldmatrix.sync.aligned.m8n8.x4.shared.b16 {%0,%1,%2,%3}, [%4];"
                 : "=r"(r[0]), "=r"(r[1]), "=r"(r[2]), "=r"(r[3]) : "r"(addr));
}
__device__ __forceinline__ void mma16816(float* c, const unsigned* a,
                                         unsigned b0, unsigned b1) {
    asm volatile(
        "mma.sync.aligned.m16n8k16.row.col.f32.f16.f16.f32 "
        "{%0,%1,%2,%3}, {%4,%5,%6,%7}, {%8,%9}, {%0,%1,%2,%3};"
        : "+f"(c[0]), "+f"(c[1]), "+f"(c[2]), "+f"(c[3])
        : "r"(a[0]), "r"(a[1]), "r"(a[2]), "r"(a[3]), "r"(b0), "r"(b1));
}
__device__ __forceinline__ unsigned short hcvt(float x) {
    return __half_as_ushort(__float2half_rn(x));
}

// ---------------- convert fp32 -> fp16 ----------------
__global__ void tohalf_kernel(const float4* __restrict__ x, uint2* __restrict__ hi, int n4)
{
    int i = blockIdx.x * blockDim.x + threadIdx.x;
    if (i >= n4) return;
    float4 v = x[i];
    uint2 hv;
    hv.x = (unsigned)hcvt(v.x) | ((unsigned)hcvt(v.y) << 16);
    hv.y = (unsigned)hcvt(v.z) | ((unsigned)hcvt(v.w) << 16);
    hi[i] = hv;
}

// ---------------- cp.async stage fill ----------------
// A: 128 rows x 32 K, B: 256 rows x 32 K. Row = 64B = 4 chunks of 16B.
__device__ __forceinline__ void fill_stage(uint32_t sb,
    const unsigned short* __restrict__ Ah, const unsigned short* __restrict__ Bh,
    int K, int tid)
{
    #pragma unroll
    for (int i = 0; i < 2; ++i) {                       // A: 512 chunks
        const int idx = (i << 8) + tid;
        const int row = idx >> 2, ch = idx & 3;
        cpasync16(sb + A_HI + row * ROWB + ch * 16, Ah + (size_t)row * K + ch * 8);
    }
    #pragma unroll
    for (int i = 0; i < 4; ++i) {                       // B: 1024 chunks
        const int idx = (i << 8) + tid;
        const int row = idx >> 2, ch = idx & 3;
        cpasync16(sb + B_HI + row * ROWB + ch * 16, Bh + (size_t)row * K + ch * 8);
    }
}

// ---------------- fp16 single-pass NT GEMM (mma.sync path) ----------------
// C[m,n] = sum_k A[m,k]*B[n,k], fp32 accumulate.
// EPI=4: fp16 out ([M,N])     EPI=1: transposed fp16 out [b][n][t]
// EPI=2: v*scale, mask==0 -> -inf, fp32 out   EPI=3: fp32 out
template<int EPI>
__global__ __launch_bounds__(256, 1)
void gemm_mma(const unsigned short* __restrict__ Ahi, const unsigned short* __restrict__ Bhi,
              float* __restrict__ outF, unsigned* __restrict__ outHi,
              unsigned short* __restrict__ outTHi,
              int N, int K, size_t sA, size_t sB, size_t sC,
              const int* __restrict__ mask, float scale)
{
    extern __shared__ char smem[];
    const uint32_t smb = smem_u32(smem);
    const int tid = threadIdx.x, lane = tid & 31, wid = tid >> 5;
    const int wm = wid & 1, wn = wid >> 1;          // 2 x 4 warp grid, warp tile 64x64
    const int mblk = blockIdx.y << 7, nblk = blockIdx.x << 8;
    const size_t bz = blockIdx.z;

    const unsigned short* pAh = Ahi + bz * sA + (size_t)mblk * K;
    const unsigned short* pBh = Bhi + bz * sB + (size_t)nblk * K;

    float acc[4][8][4];
    #pragma unroll
    for (int i = 0; i < 4; ++i)
        #pragma unroll
        for (int j = 0; j < 8; ++j)
            #pragma unroll
            for (int e = 0; e < 4; ++e) acc[i][j][e] = 0.0f;

    const int nk = K >> 5;

    #pragma unroll
    for (int s = 0; s < NSTAGE - 1; ++s) {
        fill_stage(smb + s * STG_B, pAh + s * 32, pBh + s * 32, K, tid);
        asm volatile("cp.async.commit_group;" ::: "memory");
    }

    const int lrow = lane & 15;
    const uint32_t lcoff = (lane >> 4) << 4;   // 0 or 16 bytes

    for (int kt = 0; kt < nk; ++kt) {
        asm volatile("cp.async.wait_group 1;" ::: "memory");
        __syncthreads();

        const int s2 = kt + NSTAGE - 1;
        if (s2 < nk) {
            fill_stage(smb + (s2 % NSTAGE) * STG_B, pAh + s2 * 32, pBh + s2 * 32, K, tid);
        }
        asm volatile("cp.async.commit_group;" ::: "memory");

        const uint32_t sb = smb + (kt % NSTAGE) * STG_B;
        #pragma unroll
        for (int ks = 0; ks < 2; ++ks) {
            const uint32_t koff = (ks << 5) + lcoff;
            unsigned ah[4][4], bh[4][4];
            #pragma unroll
            for (int mf = 0; mf < 4; ++mf) {
                uint32_t r = sb + (uint32_t)(wm * 64 + mf * 16 + lrow) * ROWB + koff;
                ldsm4(ah[mf], r + A_HI);
            }
            #pragma unroll
            for (int nf2 = 0; nf2 < 4; ++nf2) {
                uint32_t r = sb + (uint32_t)(wn * 64 + nf2 * 16 + lrow) * ROWB + koff;
                ldsm4(bh[nf2], r + B_HI);
            }
            #pragma unroll
            for (int mf = 0; mf < 4; ++mf) {
                #pragma unroll
                for (int nf = 0; nf < 8; ++nf) {
                    const int g = nf >> 1, s = nf & 1;
                    mma16816(acc[mf][nf], ah[mf], bh[g][s], bh[g][s + 2]);
                }
            }
        }
    }

    // ---------------- epilogue ----------------
    const float NEG_INF = __int_as_float(0xff800000);
    const int mbase = mblk + wm * 64 + (lane >> 2);
    const int nbase = nblk + wn * 64 + ((lane & 3) << 1);
    #pragma unroll
    for (int mf = 0; mf < 4; ++mf) {
        #pragma unroll
        for (int nf = 0; nf < 8; ++nf) {
            const float* c = acc[mf][nf];
            const int r0 = mbase + mf * 16;
            const int c0 = nbase + nf * 8;
            if (EPI == 2) {
                const int2 m0 = *(const int2*)(mask + (size_t)r0 * N + c0);
                const int2 m1 = *(const int2*)(mask + (size_t)(r0 + 8) * N + c0);
                float2 o0, o1;
                o0.x = m0.x ? c[0] * scale : NEG_INF;
                o0.y = m0.y ? c[1] * scale : NEG_INF;
                o1.x = m1.x ? c[2] * scale : NEG_INF;
                o1.y = m1.y ? c[3] * scale : NEG_INF;
                *(float2*)(outF + bz * sC + (size_t)r0 * N + c0)       = o0;
                *(float2*)(outF + bz * sC + (size_t)(r0 + 8) * N + c0) = o1;
            } else if (EPI == 3) {
                *(float2*)(outF + bz * sC + (size_t)r0 * N + c0)       = make_float2(c[0], c[1]);
                *(float2*)(outF + bz * sC + (size_t)(r0 + 8) * N + c0) = make_float2(c[2], c[3]);
            } else if (EPI == 4) {
                outHi[((size_t)r0 * N + c0) >> 1] =
                    (unsigned)hcvt(c[0]) | ((unsigned)hcvt(c[1]) << 16);
                outHi[((size_t)(r0 + 8) * N + c0) >> 1] =
                    (unsigned)hcvt(c[2]) | ((unsigned)hcvt(c[3]) << 16);
            } else {  // EPI == 1: VT[b][o][t]
                #pragma unroll
                for (int e = 0; e < 4; ++e) {
                    const int r = r0 + (e >> 1) * 8;
                    const int o = c0 + (e & 1);
                    const size_t idx = (((size_t)(r >> 11)) * E_ + o) * T_ + (r & (T_ - 1));
                    outTHi[idx] = hcvt(c[e]);
                }
            }
        }
    }
}

// ---------------- softmax: fp32 S row -> fp16 P ----------------
__global__ void softmax_kernel(const float* __restrict__ S, uint4* __restrict__ Phi)
{
    const int row = blockIdx.x, tid = threadIdx.x;
    const float4* src = (const float4*)(S + (size_t)row * T_);
    float4 a = src[tid * 2], b2 = src[tid * 2 + 1];
    float v[8] = {a.x, a.y, a.z, a.w, b2.x, b2.y, b2.z, b2.w};

    float mx = v[0];
    #pragma unroll
    for (int i = 1; i < 8; ++i) mx = fmaxf(mx, v[i]);
    __shared__ float red[8];
    #pragma unroll
    for (int o = 16; o > 0; o >>= 1) mx = fmaxf(mx, __shfl_xor_sync(0xffffffff, mx, o));
    if ((tid & 31) == 0) red[tid >> 5] = mx;
    __syncthreads();
    float rmax = fmaxf(fmaxf(fmaxf(red[0], red[1]), fmaxf(red[2], red[3])),
                       fmaxf(fmaxf(red[4], red[5]), fmaxf(red[6], red[7])));
    __syncthreads();

    float sum = 0.0f;
    #pragma unroll
    for (int i = 0; i < 8; ++i) { v[i] = expf(v[i] - rmax); sum += v[i]; }
    #pragma unroll
    for (int o = 16; o > 0; o >>= 1) sum += __shfl_xor_sync(0xffffffff, sum, o);
    if ((tid & 31) == 0) red[tid >> 5] = sum;
    __syncthreads();
    float tot = red[0] + red[1] + red[2] + red[3] + red[4] + red[5] + red[6] + red[7];
    float inv = 1.0f / tot;

    unsigned hw[4];
    #pragma unroll
    for (int j = 0; j < 4; ++j) {
        hw[j] = (unsigned)hcvt(v[2 * j] * inv) | ((unsigned)hcvt(v[2 * j + 1] * inv) << 16);
    }
    Phi[(size_t)row * (T_ / 8) + tid] = make_uint4(hw[0], hw[1], hw[2], hw[3]);
}

// ---------------- driver ----------------
extern "C" void kernel_launch(void* const* d_in, const int* in_sizes, int n_in,
                              void* d_out, int out_size)
{
    const float* q    = (const float*)d_in[0];
    const float* k    = (const float*)d_in[1];
    const float* v    = (const float*)d_in[2];
    const int*   mask = (const int*)  d_in[3];
    const float* Wq   = (const float*)d_in[4];
    const float* Wk   = (const float*)d_in[5];
    const float* Wv   = (const float*)d_in[6];
    float* out = (float*)d_out;

    unsigned short *qh, *kh, *vh, *Wqh, *Wkh, *Wvh;
    unsigned short *Qhi, *Khi, *VThi, *Phi;
    float* S;
    cudaGetSymbolAddress((void**)&qh,   g_qh);
    cudaGetSymbolAddress((void**)&kh,   g_kh);
    cudaGetSymbolAddress((void**)&vh,   g_vh);
    cudaGetSymbolAddress((void**)&Wqh,  g_Wq);
    cudaGetSymbolAddress((void**)&Wkh,  g_Wk);
    cudaGetSymbolAddress((void**)&Wvh,  g_Wv);
    cudaGetSymbolAddress((void**)&Qhi,  g_Qhi);
    cudaGetSymbolAddress((void**)&Khi,  g_Khi);
    cudaGetSymbolAddress((void**)&VThi, g_VThi);
    cudaGetSymbolAddress((void**)&S,    g_S);
    cudaGetSymbolAddress((void**)&Phi,  g_Phi);

    cudaFuncSetAttribute(gemm_mma<1>, cudaFuncAttributeMaxDynamicSharedMemorySize, SMEM_BYTES);
    cudaFuncSetAttribute(gemm_mma<2>, cudaFuncAttributeMaxDynamicSharedMemorySize, SMEM_BYTES);
    cudaFuncSetAttribute(gemm_mma<3>, cudaFuncAttributeMaxDynamicSharedMemorySize, SMEM_BYTES);
    cudaFuncSetAttribute(gemm_mma<4>, cudaFuncAttributeMaxDynamicSharedMemorySize, SMEM_BYTES);

    const int nx = B_ * T_ * E_ / 4;
    const int nw = E_ * E_ / 4;
    tohalf_kernel<<<(nx + 255) / 256, 256>>>((const float4*)q,  (uint2*)qh,  nx);
    tohalf_kernel<<<(nx + 255) / 256, 256>>>((const float4*)k,  (uint2*)kh,  nx);
    tohalf_kernel<<<(nx + 255) / 256, 256>>>((const float4*)v,  (uint2*)vh,  nx);
    tohalf_kernel<<<(nw + 255) / 256, 256>>>((const float4*)Wq, (uint2*)Wqh, nw);
    tohalf_kernel<<<(nw + 255) / 256, 256>>>((const float4*)Wk, (uint2*)Wkh, nw);
    tohalf_kernel<<<(nw + 255) / 256, 256>>>((const float4*)Wv, (uint2*)Wvh, nw);

    // projections: [B*T, E] = [B*T, E] x [E, E]^T
    dim3 gp(E_ / 256, (B_ * T_) / 128, 1);
    gemm_mma<4><<<gp, 256, SMEM_BYTES>>>(qh, Wqh,
        nullptr, (unsigned*)Qhi, nullptr, E_, E_, 0, 0, 0, nullptr, 0.f);
    gemm_mma<4><<<gp, 256, SMEM_BYTES>>>(kh, Wkh,
        nullptr, (unsigned*)Khi, nullptr, E_, E_, 0, 0, 0, nullptr, 0.f);
    gemm_mma<1><<<gp, 256, SMEM_BYTES>>>(vh, Wvh,
        nullptr, nullptr, VThi, E_, E_, 0, 0, 0, nullptr, 0.f);

    // scores: per batch [T,T] = Q x K^T, scaled + masked
    dim3 gs(T_ / 256, T_ / 128, B_);
    gemm_mma<2><<<gs, 256, SMEM_BYTES>>>(Qhi, Khi,
        S, nullptr, nullptr,
        T_, E_, (size_t)T_ * E_, (size_t)T_ * E_, (size_t)T_ * T_, mask, 0.03125f);

    softmax_kernel<<<B_ * T_, 256>>>(S, (uint4*)Phi);

    // out: per batch [T,E] = P x VT^T  (VT stored [o][t])
    dim3 gv(E_ / 256, T_ / 128, B_);
    gemm_mma<3><<<gv, 256, SMEM_BYTES>>>(Phi, VThi,
        out, nullptr, nullptr,
        E_, T_, (size_t)T_ * T_, (size_t)E_ * T_, (size_t)T_ * E_, nullptr, 1.f);
}